// round 5
// baseline (speedup 1.0000x reference)
#include <cuda_runtime.h>
#include <cuda_bf16.h>
#include <cstdint>

#define Nn 50000
#define Ee 600000
#define Gg 512
#define Hh 128
#define SCAN_BLKS ((Nn + 255) / 256)   // 196
#define EPSf 1e-5f

typedef unsigned long long u64;

// ---------------- device scratch (no allocations allowed) ----------------
__device__ __align__(16) float g_hw[(size_t)Nn * Hh];      // h @ W
__device__ __align__(16) float g_agg[(size_t)Nn * Hh];     // aggregated (GEMM/pool input)
__device__ __align__(16) float g_P[470 * Hh];              // projected embedding tables
__device__ __align__(16) float g_dinv[Nn];
__device__ __align__(16) float g_bnsum[3 * Hh];
__device__ __align__(16) float g_bnsq[3 * Hh];
__device__ __align__(16) float g_pooled[Gg * Hh];
__device__ __align__(16) float g_cnt[Gg];
__device__ int g_degcnt[Nn];
__device__ int g_cursor[Nn];
__device__ int g_base[Nn + 1];
__device__ int g_esrc[Ee];
__device__ int g_bsum[256];
__device__ int g_boff[256];

// ---------------- packed f32x2 helpers ----------------
__device__ __forceinline__ u64 pack2(float a) {
    u64 r; asm("mov.b64 %0, {%1, %1};" : "=l"(r) : "f"(a)); return r;
}
__device__ __forceinline__ void fma2(u64& acc, u64 a, u64 b) {
    asm("fma.rn.f32x2 %0, %1, %2, %0;" : "+l"(acc) : "l"(a), "l"(b));
}
__device__ __forceinline__ float2 unpack2(u64 v) {
    float2 f; asm("mov.b64 {%0, %1}, %2;" : "=f"(f.x), "=f"(f.y) : "l"(v)); return f;
}

// ---------------- init: zero accumulators ----------------
__global__ void k_init() {
    int i = blockIdx.x * blockDim.x + threadIdx.x;   // 65536 threads
    if (i < Nn) { g_degcnt[i] = 0; g_cursor[i] = 0; }
    if (i < Gg * Hh) g_pooled[i] = 0.0f;
    if (i < Gg) g_cnt[i] = 0.0f;
    if (i < 3 * Hh) { g_bnsum[i] = 0.0f; g_bnsq[i] = 0.0f; }
}

// ---------------- degree count + graph-size count ----------------
__global__ void k_count(const int* __restrict__ ei, const int* __restrict__ batch) {
    int j = blockIdx.x * blockDim.x + threadIdx.x;
    if (j < Ee) atomicAdd(&g_degcnt[ei[Ee + j]], 1);
    if (j < Nn) atomicAdd(&g_cnt[batch[j]], 1.0f);
}

// ---------------- exclusive scan of degcnt -> g_base ----------------
__global__ void k_scan1() {
    __shared__ int sh[256];
    int tid = threadIdx.x;
    int i = blockIdx.x * 256 + tid;
    int v = (i < Nn) ? g_degcnt[i] : 0;
    sh[tid] = v; __syncthreads();
    for (int off = 1; off < 256; off <<= 1) {
        int y = (tid >= off) ? sh[tid - off] : 0;
        __syncthreads();
        sh[tid] += y;
        __syncthreads();
    }
    if (i < Nn) g_base[i] = sh[tid] - v;            // exclusive within block
    if (tid == 255) g_bsum[blockIdx.x] = sh[255];   // block total
}
__global__ void k_scan2() {
    __shared__ int sh[256];
    int tid = threadIdx.x;
    int v = (tid < SCAN_BLKS) ? g_bsum[tid] : 0;
    sh[tid] = v; __syncthreads();
    for (int off = 1; off < 256; off <<= 1) {
        int y = (tid >= off) ? sh[tid - off] : 0;
        __syncthreads();
        sh[tid] += y;
        __syncthreads();
    }
    g_boff[tid] = sh[tid] - v;                      // exclusive block offsets
}
// scan finalize + dinv fused
__global__ void k_scan3() {
    int i = blockIdx.x * 256 + threadIdx.x;
    if (i < Nn) {
        g_base[i] += g_boff[blockIdx.x];
        g_dinv[i] = rsqrtf((float)g_degcnt[i] + 1.0f);
    }
    if (i == 0) g_base[Nn] = Ee;
}

// ---------------- place edges into CSR-by-dst ----------------
__global__ void k_place(const int* __restrict__ ei) {
    int e = blockIdx.x * blockDim.x + threadIdx.x;
    if (e >= Ee) return;
    int dst = ei[Ee + e];
    int pos = g_base[dst] + atomicAdd(&g_cursor[dst], 1);
    g_esrc[pos] = ei[e];
}

// ---------------- project all embedding tables through W1 (one kernel) ----------------
__global__ void k_projall(const float* __restrict__ emb0, const float* __restrict__ emb1,
                          const float* __restrict__ emb2, const float* __restrict__ emb5,
                          const float* __restrict__ W1) {
    int bv = blockIdx.x;              // 0..469
    int c = threadIdx.x;
    const float* emb; int koff, v;
    if (bv < 96)       { emb = emb0; koff = 1;  v = bv; }
    else if (bv < 192) { emb = emb1; koff = 33; v = bv - 96; }
    else if (bv < 288) { emb = emb2; koff = 65; v = bv - 192; }
    else               { emb = emb5; koff = 97; v = bv - 288; }
    float acc = 0.0f;
#pragma unroll
    for (int j = 0; j < 32; j++)
        acc += emb[v * 32 + j] * W1[(koff + j) * Hh + c];
    g_P[(size_t)bv * Hh + c] = acc;
}

// ---------------- layer-1 hw (embedding lookup form) ----------------
__global__ void k_layer1(const float* __restrict__ x, const float* __restrict__ W1) {
    int i = blockIdx.x;
    int c = threadIdx.x;
    const float* xr = x + (size_t)i * 5;
    float pos = xr[0];
    int i0 = (int)xr[1], i1 = (int)xr[2], i2 = (int)xr[3], i5 = (int)xr[4];
    float v = pos * W1[c]
            + g_P[(size_t)i0 * Hh + c]
            + g_P[(size_t)(96 + i1) * Hh + c]
            + g_P[(size_t)(192 + i2) * Hh + c]
            + g_P[(size_t)(288 + i5) * Hh + c];
    g_hw[(size_t)i * Hh + c] = v;
}

// ---------------- fused aggregation + self-loop + bias + BN partial stats ------
// warp per node; neighbors unrolled x4 with independent loads; dinv[dst]
// factored out of the inner loop. Block reduces BN sums and RED-adds once.
__global__ void __launch_bounds__(256) k_gather(int layer, const float* __restrict__ bias) {
    __shared__ float s_sum[8][132];
    __shared__ float s_sq[8][132];
    int tid = threadIdx.x;
    int wp = tid >> 5;
    int lane = tid & 31;
    int gw = blockIdx.x * 8 + wp;

    float4 acc = make_float4(0.f, 0.f, 0.f, 0.f);
    float4 outv = make_float4(0.f, 0.f, 0.f, 0.f);
    bool active = (gw < Nn);
    if (active) {
        int s = g_base[gw], e = g_base[gw + 1];
        float di = g_dinv[gw];
        int t = s;
        for (; t + 4 <= e; t += 4) {
            int s0 = g_esrc[t + 0], s1 = g_esrc[t + 1];
            int s2 = g_esrc[t + 2], s3 = g_esrc[t + 3];
            float n0 = g_dinv[s0], n1 = g_dinv[s1];
            float n2 = g_dinv[s2], n3 = g_dinv[s3];
            float4 v0 = *(const float4*)(g_hw + (size_t)s0 * Hh + lane * 4);
            float4 v1 = *(const float4*)(g_hw + (size_t)s1 * Hh + lane * 4);
            float4 v2 = *(const float4*)(g_hw + (size_t)s2 * Hh + lane * 4);
            float4 v3 = *(const float4*)(g_hw + (size_t)s3 * Hh + lane * 4);
            acc.x += (v0.x * n0 + v1.x * n1) + (v2.x * n2 + v3.x * n3);
            acc.y += (v0.y * n0 + v1.y * n1) + (v2.y * n2 + v3.y * n3);
            acc.z += (v0.z * n0 + v1.z * n1) + (v2.z * n2 + v3.z * n3);
            acc.w += (v0.w * n0 + v1.w * n1) + (v2.w * n2 + v3.w * n3);
        }
        for (; t < e; t++) {
            int s0 = g_esrc[t];
            float n0 = g_dinv[s0];
            float4 v0 = *(const float4*)(g_hw + (size_t)s0 * Hh + lane * 4);
            acc.x += v0.x * n0; acc.y += v0.y * n0;
            acc.z += v0.z * n0; acc.w += v0.w * n0;
        }
        // self term + bias
        float d2 = di * di;
        float4 hv = *(const float4*)(g_hw + (size_t)gw * Hh + lane * 4);
        float4 bv = *(const float4*)(bias + lane * 4);
        outv.x = acc.x * di + hv.x * d2 + bv.x;
        outv.y = acc.y * di + hv.y * d2 + bv.y;
        outv.z = acc.z * di + hv.z * d2 + bv.z;
        outv.w = acc.w * di + hv.w * d2 + bv.w;
        *(float4*)(g_agg + (size_t)gw * Hh + lane * 4) = outv;
    }
    // BN partial sums: per-warp row into smem, then block-reduce, then RED
    s_sum[wp][lane * 4 + 0] = outv.x; s_sq[wp][lane * 4 + 0] = outv.x * outv.x;
    s_sum[wp][lane * 4 + 1] = outv.y; s_sq[wp][lane * 4 + 1] = outv.y * outv.y;
    s_sum[wp][lane * 4 + 2] = outv.z; s_sq[wp][lane * 4 + 2] = outv.z * outv.z;
    s_sum[wp][lane * 4 + 3] = outv.w; s_sq[wp][lane * 4 + 3] = outv.w * outv.w;
    __syncthreads();
    if (tid < 128) {
        float s = 0.f, q = 0.f;
#pragma unroll
        for (int w = 0; w < 8; w++) { s += s_sum[w][tid]; q += s_sq[w][tid]; }
        atomicAdd(&g_bnsum[layer * Hh + tid], s);
        atomicAdd(&g_bnsq[layer * Hh + tid], q);
    }
}

// ---------------- fused GEMM: relu(bn(A)) @ W -> hw ----------------
// BN scale/shift computed in-block from global sums (no separate bnfin launch).
// block tile 128 rows x 128 cols, 256 threads, 8x8 outputs/thread, f32x2 FMAs
#define GEMM_SMEM (128 * 132 * 4 + 128 * 128 * 4)
__global__ void __launch_bounds__(256, 1)
k_gemm(int layer, const float* __restrict__ gamma, const float* __restrict__ beta,
       const float* __restrict__ W) {
    extern __shared__ float smem[];
    float* As = smem;                 // 128 x 132 (padded)
    float* Ws = smem + 128 * 132;     // 128 x 128
    __shared__ float s_scale[128];
    __shared__ float s_shift[128];
    int tid = threadIdx.x;
    int row0 = blockIdx.x * 128;

    if (tid < 128) {
        float mean = g_bnsum[layer * Hh + tid] * (1.0f / Nn);
        float var = g_bnsq[layer * Hh + tid] * (1.0f / Nn) - mean * mean;
        float sc = gamma[tid] * rsqrtf(var + EPSf);
        s_scale[tid] = sc;
        s_shift[tid] = beta[tid] - mean * sc;
    }

    // load W (16384 floats) as float4
    for (int t = tid; t < 128 * 128 / 4; t += 256)
        ((float4*)Ws)[t] = ((const float4*)W)[t];
    __syncthreads();

    // load A tile with BN+ReLU transform, zero-pad OOB rows
    for (int t = tid; t < 128 * 32; t += 256) {
        int r = t >> 5, q = t & 31;
        int grow = row0 + r;
        float4 v = make_float4(0.f, 0.f, 0.f, 0.f);
        if (grow < Nn) {
            v = ((const float4*)(g_agg + (size_t)grow * Hh))[q];
            float4 sc = ((const float4*)s_scale)[q];
            float4 sh = ((const float4*)s_shift)[q];
            v.x = fmaxf(v.x * sc.x + sh.x, 0.f);
            v.y = fmaxf(v.y * sc.y + sh.y, 0.f);
            v.z = fmaxf(v.z * sc.z + sh.z, 0.f);
            v.w = fmaxf(v.w * sc.w + sh.w, 0.f);
        }
        *(float4*)(As + r * 132 + q * 4) = v;
    }
    __syncthreads();

    int tx = tid & 15;   // col group: cols tx*8 .. tx*8+7
    int ty = tid >> 4;   // row group: rows ty*8 .. ty*8+7

    u64 acc[8][4];
#pragma unroll
    for (int r = 0; r < 8; r++)
#pragma unroll
        for (int p = 0; p < 4; p++) acc[r][p] = 0ull;

    const float* As_r = As + ty * 8 * 132;
#pragma unroll 4
    for (int k = 0; k < 128; k++) {
        const u64* wk = (const u64*)(Ws + k * 128 + tx * 8);
        u64 w0 = wk[0], w1 = wk[1], w2 = wk[2], w3 = wk[3];
#pragma unroll
        for (int r = 0; r < 8; r++) {
            u64 a2 = pack2(As_r[r * 132 + k]);
            fma2(acc[r][0], a2, w0);
            fma2(acc[r][1], a2, w1);
            fma2(acc[r][2], a2, w2);
            fma2(acc[r][3], a2, w3);
        }
    }

#pragma unroll
    for (int r = 0; r < 8; r++) {
        int grow = row0 + ty * 8 + r;
        if (grow >= Nn) continue;
        float* hwp = g_hw + (size_t)grow * Hh + tx * 8;
#pragma unroll
        for (int p = 0; p < 4; p++) {
            float2 f = unpack2(acc[r][p]);
            *(float2*)(hwp + 2 * p) = f;
        }
    }
}

// ---------------- pooling: batch is sorted -> run-length accumulate ----------------
// BN(layer 2) scale/shift computed in-block.
__global__ void k_pool(const int* __restrict__ batch,
                       const float* __restrict__ gamma, const float* __restrict__ beta) {
    __shared__ int sb[128];
    int c = threadIdx.x;
    int r0 = blockIdx.x * 128;
    int nrows = min(128, Nn - r0);
    if (c < nrows) sb[c] = batch[r0 + c];
    float mean = g_bnsum[2 * Hh + c] * (1.0f / Nn);
    float var = g_bnsq[2 * Hh + c] * (1.0f / Nn) - mean * mean;
    float sc = gamma[c] * rsqrtf(var + EPSf);
    float sh = beta[c] - mean * sc;
    __syncthreads();
    float acc = 0.f;
    int cur = sb[0];
    for (int r = 0; r < nrows; r++) {
        int gr = sb[r];
        if (gr != cur) { atomicAdd(&g_pooled[cur * Hh + c], acc); acc = 0.f; cur = gr; }
        float v = g_agg[(size_t)(r0 + r) * Hh + c];
        acc += fmaxf(v * sc + sh, 0.f);
    }
    atomicAdd(&g_pooled[cur * Hh + c], acc);
}

// ---------------- final FC: (pooled / cnt) @ fcW + fcb ----------------
__global__ void k_fc(const float* __restrict__ fcW, const float* __restrict__ fcb,
                     float* __restrict__ out) {
    int g = blockIdx.x, c = threadIdx.x;
    float v = g_pooled[g * Hh + c] / fmaxf(g_cnt[g], 1.0f);
    __shared__ float s0[128], s1[128], s2[128];
    s0[c] = v * fcW[c * 3 + 0];
    s1[c] = v * fcW[c * 3 + 1];
    s2[c] = v * fcW[c * 3 + 2];
    __syncthreads();
    for (int off = 64; off > 0; off >>= 1) {
        if (c < off) { s0[c] += s0[c + off]; s1[c] += s1[c + off]; s2[c] += s2[c + off]; }
        __syncthreads();
    }
    if (c == 0) {
        out[g * 3 + 0] = s0[0] + fcb[0];
        out[g * 3 + 1] = s1[0] + fcb[1];
        out[g * 3 + 2] = s2[0] + fcb[2];
    }
}

// ---------------- launch ----------------
extern "C" void kernel_launch(void* const* d_in, const int* in_sizes, int n_in,
                              void* d_out, int out_size) {
    const float* x     = (const float*)d_in[0];
    const int*   ei    = (const int*)  d_in[1];
    const int*   batch = (const int*)  d_in[2];
    const float* emb0  = (const float*)d_in[3];
    const float* emb1  = (const float*)d_in[4];
    const float* emb2  = (const float*)d_in[5];
    const float* emb5  = (const float*)d_in[6];
    const float* W1    = (const float*)d_in[7];
    const float* b1    = (const float*)d_in[8];
    const float* W2    = (const float*)d_in[9];
    const float* b2    = (const float*)d_in[10];
    const float* W3    = (const float*)d_in[11];
    const float* b3    = (const float*)d_in[12];
    const float* g1    = (const float*)d_in[13];
    const float* be1   = (const float*)d_in[14];
    const float* g2    = (const float*)d_in[15];
    const float* be2   = (const float*)d_in[16];
    const float* g3    = (const float*)d_in[17];
    const float* be3   = (const float*)d_in[18];
    const float* fcW   = (const float*)d_in[19];
    const float* fcb   = (const float*)d_in[20];
    float* out = (float*)d_out;

    cudaFuncSetAttribute(k_gemm, cudaFuncAttributeMaxDynamicSharedMemorySize, GEMM_SMEM);

    const int nblk = (Nn + 127) / 128;          // 391
    const int eblk = (Ee + 255) / 256;          // 2344
    const int gblk = (Nn + 7) / 8;              // gather blocks (8 warps = 8 nodes)

    // graph preprocessing
    k_init<<<256, 256>>>();
    k_count<<<eblk, 256>>>(ei, batch);
    k_scan1<<<SCAN_BLKS, 256>>>();
    k_scan2<<<1, 256>>>();
    k_scan3<<<SCAN_BLKS, 256>>>();
    k_place<<<eblk, 256>>>(ei);

    // layer 1 (embedding-decomposed GEMM)
    k_projall<<<470, 128>>>(emb0, emb1, emb2, emb5, W1);
    k_layer1<<<Nn, 128>>>(x, W1);
    k_gather<<<gblk, 256>>>(0, b1);

    // layer 2
    k_gemm<<<nblk, 256, GEMM_SMEM>>>(0, g1, be1, W2);
    k_gather<<<gblk, 256>>>(1, b2);

    // layer 3
    k_gemm<<<nblk, 256, GEMM_SMEM>>>(1, g2, be2, W3);
    k_gather<<<gblk, 256>>>(2, b3);

    // pooling + classifier
    k_pool<<<nblk, 128>>>(batch, g3, be3);
    k_fc<<<Gg, 128>>>(fcW, fcb, out);
}

// round 6
// speedup vs baseline: 1.1356x; 1.1356x over previous
#include <cuda_runtime.h>
#include <cuda_fp16.h>
#include <cstdint>

#define Nn 50000
#define Ee 600000
#define Gg 512
#define Hh 128
#define SCAN_BLKS ((Nn + 255) / 256)   // 196
#define EPSf 1e-5f

typedef unsigned long long u64;

// ---------------- device scratch (no allocations allowed) ----------------
__device__ __align__(16) __half2 g_hwh[(size_t)Nn * 64];   // h @ W in fp16 (row = 256B)
__device__ __align__(16) float g_agg[(size_t)Nn * Hh];     // aggregated (GEMM/pool input)
__device__ __align__(16) float g_P[470 * Hh];              // projected embedding tables
__device__ __align__(16) float g_dinv[Nn];
__device__ __align__(16) float g_bnsum[3 * Hh];
__device__ __align__(16) float g_bnsq[3 * Hh];
__device__ __align__(16) float g_pooled[Gg * Hh];
__device__ __align__(16) float g_cnt[Gg];
__device__ int g_degcnt[Nn];
__device__ int g_cursor[Nn];
__device__ int g_base[Nn + 1];
__device__ int g_esrc[Ee];
__device__ int g_bsum[256];

// ---------------- packed f32x2 helpers ----------------
__device__ __forceinline__ u64 pack2(float a) {
    u64 r; asm("mov.b64 %0, {%1, %1};" : "=l"(r) : "f"(a)); return r;
}
__device__ __forceinline__ void fma2(u64& acc, u64 a, u64 b) {
    asm("fma.rn.f32x2 %0, %1, %2, %0;" : "+l"(acc) : "l"(a), "l"(b));
}
__device__ __forceinline__ float2 unpack2(u64 v) {
    float2 f; asm("mov.b64 {%0, %1}, %2;" : "=f"(f.x), "=f"(f.y) : "l"(v)); return f;
}

// ---------------- init: zero accumulators ----------------
__global__ void k_init() {
    int i = blockIdx.x * blockDim.x + threadIdx.x;   // 65536 threads
    if (i < Nn) { g_degcnt[i] = 0; g_cursor[i] = 0; }
    if (i < Gg * Hh) g_pooled[i] = 0.0f;
    if (i < Gg) g_cnt[i] = 0.0f;
    if (i < 3 * Hh) { g_bnsum[i] = 0.0f; g_bnsq[i] = 0.0f; }
}

// ---------------- degree count + graph-size count ----------------
__global__ void k_count(const int* __restrict__ ei, const int* __restrict__ batch) {
    int j = blockIdx.x * blockDim.x + threadIdx.x;
    if (j < Ee) atomicAdd(&g_degcnt[ei[Ee + j]], 1);
    if (j < Nn) atomicAdd(&g_cnt[batch[j]], 1.0f);
}

// ---------------- two-level exclusive scan of degcnt -> g_base ----------------
__global__ void k_scan1() {
    __shared__ int sh[256];
    int tid = threadIdx.x;
    int i = blockIdx.x * 256 + tid;
    int v = (i < Nn) ? g_degcnt[i] : 0;
    sh[tid] = v; __syncthreads();
    for (int off = 1; off < 256; off <<= 1) {
        int y = (tid >= off) ? sh[tid - off] : 0;
        __syncthreads();
        sh[tid] += y;
        __syncthreads();
    }
    if (i < Nn) g_base[i] = sh[tid] - v;            // exclusive within block
    if (tid == 255) g_bsum[blockIdx.x] = sh[255];   // block total
}
// finalize: each block redundantly scans the 196 block sums (kills the serial
// single-block scan2 launch), adds its prefix, and computes dinv.
__global__ void k_scan3() {
    __shared__ int sh[256];
    int tid = threadIdx.x;
    int bv = (tid < SCAN_BLKS) ? g_bsum[tid] : 0;
    sh[tid] = bv; __syncthreads();
    for (int off = 1; off < 256; off <<= 1) {
        int y = (tid >= off) ? sh[tid - off] : 0;
        __syncthreads();
        sh[tid] += y;
        __syncthreads();
    }
    int boff = sh[blockIdx.x] - g_bsum[blockIdx.x]; // exclusive offset for this block
    int i = blockIdx.x * 256 + tid;
    if (i < Nn) {
        g_base[i] += boff;
        g_dinv[i] = rsqrtf((float)g_degcnt[i] + 1.0f);
    }
    if (i == 0) g_base[Nn] = Ee;
}

// ---------------- place edges into CSR-by-dst ----------------
__global__ void k_place(const int* __restrict__ ei) {
    int e = blockIdx.x * blockDim.x + threadIdx.x;
    if (e >= Ee) return;
    int dst = ei[Ee + e];
    int pos = g_base[dst] + atomicAdd(&g_cursor[dst], 1);
    g_esrc[pos] = ei[e];
}

// ---------------- project all embedding tables through W1 (one kernel) ----------------
__global__ void k_projall(const float* __restrict__ emb0, const float* __restrict__ emb1,
                          const float* __restrict__ emb2, const float* __restrict__ emb5,
                          const float* __restrict__ W1) {
    int bv = blockIdx.x;              // 0..469
    int c = threadIdx.x;
    const float* emb; int koff, v;
    if (bv < 96)       { emb = emb0; koff = 1;  v = bv; }
    else if (bv < 192) { emb = emb1; koff = 33; v = bv - 96; }
    else if (bv < 288) { emb = emb2; koff = 65; v = bv - 192; }
    else               { emb = emb5; koff = 97; v = bv - 288; }
    float acc = 0.0f;
#pragma unroll
    for (int j = 0; j < 32; j++)
        acc += emb[v * 32 + j] * W1[(koff + j) * Hh + c];
    g_P[(size_t)bv * Hh + c] = acc;
}

// ---------------- layer-1 hw (embedding lookup form), fp16 output ----------------
// 256 threads = 4 nodes x 64 threads; each thread computes 2 channels -> 1 half2
__global__ void k_layer1(const float* __restrict__ x, const float* __restrict__ W1) {
    int tid = threadIdx.x;
    int node = blockIdx.x * 4 + (tid >> 6);
    if (node >= Nn) return;
    int c2 = tid & 63;                // half2 index; channels 2*c2, 2*c2+1
    int c0 = c2 * 2;
    const float* xr = x + (size_t)node * 5;
    float pos = xr[0];
    int i0 = (int)xr[1], i1 = (int)xr[2], i2 = (int)xr[3], i5 = (int)xr[4];
    const float* p0 = g_P + (size_t)i0 * Hh;
    const float* p1 = g_P + (size_t)(96 + i1) * Hh;
    const float* p2 = g_P + (size_t)(192 + i2) * Hh;
    const float* p5 = g_P + (size_t)(288 + i5) * Hh;
    float va = pos * W1[c0]     + p0[c0]     + p1[c0]     + p2[c0]     + p5[c0];
    float vb = pos * W1[c0 + 1] + p0[c0 + 1] + p1[c0 + 1] + p2[c0 + 1] + p5[c0 + 1];
    g_hwh[(size_t)node * 64 + c2] = __floats2half2_rn(va, vb);
}

// ---------------- fused aggregation + self-loop + bias + BN partial stats ------
// warp per node over CSR; hw rows are fp16 (256B), lane handles 4 channels (8B).
__global__ void __launch_bounds__(256) k_gather(int layer, const float* __restrict__ bias) {
    __shared__ float s_sum[8][132];
    __shared__ float s_sq[8][132];
    int tid = threadIdx.x;
    int wp = tid >> 5;
    int lane = tid & 31;
    int gw = blockIdx.x * 8 + wp;

    float4 outv = make_float4(0.f, 0.f, 0.f, 0.f);
    if (gw < Nn) {
        int s = g_base[gw], e = g_base[gw + 1];
        float di = g_dinv[gw];
        float4 acc = make_float4(0.f, 0.f, 0.f, 0.f);
        int t = s;
        for (; t + 4 <= e; t += 4) {
            int s0 = g_esrc[t + 0], s1 = g_esrc[t + 1];
            int s2 = g_esrc[t + 2], s3 = g_esrc[t + 3];
            float n0 = g_dinv[s0], n1 = g_dinv[s1];
            float n2 = g_dinv[s2], n3 = g_dinv[s3];
            uint2 r0 = *(const uint2*)(g_hwh + (size_t)s0 * 64 + lane * 2);
            uint2 r1 = *(const uint2*)(g_hwh + (size_t)s1 * 64 + lane * 2);
            uint2 r2 = *(const uint2*)(g_hwh + (size_t)s2 * 64 + lane * 2);
            uint2 r3 = *(const uint2*)(g_hwh + (size_t)s3 * 64 + lane * 2);
            float2 a0 = __half22float2(*(__half2*)&r0.x), b0 = __half22float2(*(__half2*)&r0.y);
            float2 a1 = __half22float2(*(__half2*)&r1.x), b1 = __half22float2(*(__half2*)&r1.y);
            float2 a2 = __half22float2(*(__half2*)&r2.x), b2 = __half22float2(*(__half2*)&r2.y);
            float2 a3 = __half22float2(*(__half2*)&r3.x), b3 = __half22float2(*(__half2*)&r3.y);
            acc.x += (a0.x * n0 + a1.x * n1) + (a2.x * n2 + a3.x * n3);
            acc.y += (a0.y * n0 + a1.y * n1) + (a2.y * n2 + a3.y * n3);
            acc.z += (b0.x * n0 + b1.x * n1) + (b2.x * n2 + b3.x * n3);
            acc.w += (b0.y * n0 + b1.y * n1) + (b2.y * n2 + b3.y * n3);
        }
        for (; t < e; t++) {
            int s0 = g_esrc[t];
            float n0 = g_dinv[s0];
            uint2 r0 = *(const uint2*)(g_hwh + (size_t)s0 * 64 + lane * 2);
            float2 a0 = __half22float2(*(__half2*)&r0.x), b0 = __half22float2(*(__half2*)&r0.y);
            acc.x += a0.x * n0; acc.y += a0.y * n0;
            acc.z += b0.x * n0; acc.w += b0.y * n0;
        }
        // self term + bias
        float d2 = di * di;
        uint2 rs = *(const uint2*)(g_hwh + (size_t)gw * 64 + lane * 2);
        float2 ha = __half22float2(*(__half2*)&rs.x), hb = __half22float2(*(__half2*)&rs.y);
        float4 bv = *(const float4*)(bias + lane * 4);
        outv.x = acc.x * di + ha.x * d2 + bv.x;
        outv.y = acc.y * di + ha.y * d2 + bv.y;
        outv.z = acc.z * di + hb.x * d2 + bv.z;
        outv.w = acc.w * di + hb.y * d2 + bv.w;
        *(float4*)(g_agg + (size_t)gw * Hh + lane * 4) = outv;
    }
    // BN partial sums: per-warp row into smem, block-reduce, one RED per channel
    s_sum[wp][lane * 4 + 0] = outv.x; s_sq[wp][lane * 4 + 0] = outv.x * outv.x;
    s_sum[wp][lane * 4 + 1] = outv.y; s_sq[wp][lane * 4 + 1] = outv.y * outv.y;
    s_sum[wp][lane * 4 + 2] = outv.z; s_sq[wp][lane * 4 + 2] = outv.z * outv.z;
    s_sum[wp][lane * 4 + 3] = outv.w; s_sq[wp][lane * 4 + 3] = outv.w * outv.w;
    __syncthreads();
    if (tid < 128) {
        float s = 0.f, q = 0.f;
#pragma unroll
        for (int w = 0; w < 8; w++) { s += s_sum[w][tid]; q += s_sq[w][tid]; }
        atomicAdd(&g_bnsum[layer * Hh + tid], s);
        atomicAdd(&g_bnsq[layer * Hh + tid], q);
    }
}

// ---------------- fused GEMM: relu(bn(A)) @ W -> hw (fp16) ----------------
// BN scale/shift computed in-block from global sums.
// block tile 128 rows x 128 cols, 256 threads, 8x8 outputs/thread, f32x2 FMAs
#define GEMM_SMEM (128 * 132 * 4 + 128 * 128 * 4)
__global__ void __launch_bounds__(256, 1)
k_gemm(int layer, const float* __restrict__ gamma, const float* __restrict__ beta,
       const float* __restrict__ W) {
    extern __shared__ float smem[];
    float* As = smem;                 // 128 x 132 (padded)
    float* Ws = smem + 128 * 132;     // 128 x 128
    __shared__ float s_scale[128];
    __shared__ float s_shift[128];
    int tid = threadIdx.x;
    int row0 = blockIdx.x * 128;

    if (tid < 128) {
        float mean = g_bnsum[layer * Hh + tid] * (1.0f / Nn);
        float var = g_bnsq[layer * Hh + tid] * (1.0f / Nn) - mean * mean;
        float sc = gamma[tid] * rsqrtf(var + EPSf);
        s_scale[tid] = sc;
        s_shift[tid] = beta[tid] - mean * sc;
    }

    // load W (16384 floats) as float4
    for (int t = tid; t < 128 * 128 / 4; t += 256)
        ((float4*)Ws)[t] = ((const float4*)W)[t];
    __syncthreads();

    // load A tile with BN+ReLU transform, zero-pad OOB rows
    for (int t = tid; t < 128 * 32; t += 256) {
        int r = t >> 5, q = t & 31;
        int grow = row0 + r;
        float4 v = make_float4(0.f, 0.f, 0.f, 0.f);
        if (grow < Nn) {
            v = ((const float4*)(g_agg + (size_t)grow * Hh))[q];
            float4 sc = ((const float4*)s_scale)[q];
            float4 sh = ((const float4*)s_shift)[q];
            v.x = fmaxf(v.x * sc.x + sh.x, 0.f);
            v.y = fmaxf(v.y * sc.y + sh.y, 0.f);
            v.z = fmaxf(v.z * sc.z + sh.z, 0.f);
            v.w = fmaxf(v.w * sc.w + sh.w, 0.f);
        }
        *(float4*)(As + r * 132 + q * 4) = v;
    }
    __syncthreads();

    int tx = tid & 15;   // col group: cols tx*8 .. tx*8+7
    int ty = tid >> 4;   // row group: rows ty*8 .. ty*8+7

    u64 acc[8][4];
#pragma unroll
    for (int r = 0; r < 8; r++)
#pragma unroll
        for (int p = 0; p < 4; p++) acc[r][p] = 0ull;

    const float* As_r = As + ty * 8 * 132;
#pragma unroll 4
    for (int k = 0; k < 128; k++) {
        const u64* wk = (const u64*)(Ws + k * 128 + tx * 8);
        u64 w0 = wk[0], w1 = wk[1], w2 = wk[2], w3 = wk[3];
#pragma unroll
        for (int r = 0; r < 8; r++) {
            u64 a2 = pack2(As_r[r * 132 + k]);
            fma2(acc[r][0], a2, w0);
            fma2(acc[r][1], a2, w1);
            fma2(acc[r][2], a2, w2);
            fma2(acc[r][3], a2, w3);
        }
    }

    // epilogue: convert to fp16, one 16B store per row per thread
#pragma unroll
    for (int r = 0; r < 8; r++) {
        int grow = row0 + ty * 8 + r;
        if (grow >= Nn) continue;
        uint4 u;
        {
            float2 f = unpack2(acc[r][0]); __half2 h = __floats2half2_rn(f.x, f.y);
            u.x = *reinterpret_cast<unsigned*>(&h);
        }
        {
            float2 f = unpack2(acc[r][1]); __half2 h = __floats2half2_rn(f.x, f.y);
            u.y = *reinterpret_cast<unsigned*>(&h);
        }
        {
            float2 f = unpack2(acc[r][2]); __half2 h = __floats2half2_rn(f.x, f.y);
            u.z = *reinterpret_cast<unsigned*>(&h);
        }
        {
            float2 f = unpack2(acc[r][3]); __half2 h = __floats2half2_rn(f.x, f.y);
            u.w = *reinterpret_cast<unsigned*>(&h);
        }
        *(uint4*)(g_hwh + (size_t)grow * 64 + tx * 4) = u;
    }
}

// ---------------- pooling: batch is sorted -> run-length accumulate ----------------
// BN(layer 2) scale/shift computed in-block.
__global__ void k_pool(const int* __restrict__ batch,
                       const float* __restrict__ gamma, const float* __restrict__ beta) {
    __shared__ int sb[128];
    int c = threadIdx.x;
    int r0 = blockIdx.x * 128;
    int nrows = min(128, Nn - r0);
    if (c < nrows) sb[c] = batch[r0 + c];
    float mean = g_bnsum[2 * Hh + c] * (1.0f / Nn);
    float var = g_bnsq[2 * Hh + c] * (1.0f / Nn) - mean * mean;
    float sc = gamma[c] * rsqrtf(var + EPSf);
    float sh = beta[c] - mean * sc;
    __syncthreads();
    float acc = 0.f;
    int cur = sb[0];
    for (int r = 0; r < nrows; r++) {
        int gr = sb[r];
        if (gr != cur) { atomicAdd(&g_pooled[cur * Hh + c], acc); acc = 0.f; cur = gr; }
        float v = g_agg[(size_t)(r0 + r) * Hh + c];
        acc += fmaxf(v * sc + sh, 0.f);
    }
    atomicAdd(&g_pooled[cur * Hh + c], acc);
}

// ---------------- final FC: (pooled / cnt) @ fcW + fcb ----------------
__global__ void k_fc(const float* __restrict__ fcW, const float* __restrict__ fcb,
                     float* __restrict__ out) {
    int g = blockIdx.x, c = threadIdx.x;
    float v = g_pooled[g * Hh + c] / fmaxf(g_cnt[g], 1.0f);
    __shared__ float s0[128], s1[128], s2[128];
    s0[c] = v * fcW[c * 3 + 0];
    s1[c] = v * fcW[c * 3 + 1];
    s2[c] = v * fcW[c * 3 + 2];
    __syncthreads();
    for (int off = 64; off > 0; off >>= 1) {
        if (c < off) { s0[c] += s0[c + off]; s1[c] += s1[c + off]; s2[c] += s2[c + off]; }
        __syncthreads();
    }
    if (c == 0) {
        out[g * 3 + 0] = s0[0] + fcb[0];
        out[g * 3 + 1] = s1[0] + fcb[1];
        out[g * 3 + 2] = s2[0] + fcb[2];
    }
}

// ---------------- launch ----------------
extern "C" void kernel_launch(void* const* d_in, const int* in_sizes, int n_in,
                              void* d_out, int out_size) {
    const float* x     = (const float*)d_in[0];
    const int*   ei    = (const int*)  d_in[1];
    const int*   batch = (const int*)  d_in[2];
    const float* emb0  = (const float*)d_in[3];
    const float* emb1  = (const float*)d_in[4];
    const float* emb2  = (const float*)d_in[5];
    const float* emb5  = (const float*)d_in[6];
    const float* W1    = (const float*)d_in[7];
    const float* b1    = (const float*)d_in[8];
    const float* W2    = (const float*)d_in[9];
    const float* b2    = (const float*)d_in[10];
    const float* W3    = (const float*)d_in[11];
    const float* b3    = (const float*)d_in[12];
    const float* g1    = (const float*)d_in[13];
    const float* be1   = (const float*)d_in[14];
    const float* g2    = (const float*)d_in[15];
    const float* be2   = (const float*)d_in[16];
    const float* g3    = (const float*)d_in[17];
    const float* be3   = (const float*)d_in[18];
    const float* fcW   = (const float*)d_in[19];
    const float* fcb   = (const float*)d_in[20];
    float* out = (float*)d_out;

    cudaFuncSetAttribute(k_gemm, cudaFuncAttributeMaxDynamicSharedMemorySize, GEMM_SMEM);

    const int nblk = (Nn + 127) / 128;          // 391
    const int eblk = (Ee + 255) / 256;          // 2344
    const int gblk = (Nn + 7) / 8;              // gather blocks (8 warps = 8 nodes)

    // graph preprocessing
    k_init<<<256, 256>>>();
    k_count<<<eblk, 256>>>(ei, batch);
    k_scan1<<<SCAN_BLKS, 256>>>();
    k_scan3<<<SCAN_BLKS, 256>>>();
    k_place<<<eblk, 256>>>(ei);

    // layer 1 (embedding-decomposed GEMM)
    k_projall<<<470, 128>>>(emb0, emb1, emb2, emb5, W1);
    k_layer1<<<(Nn + 3) / 4, 256>>>(x, W1);
    k_gather<<<gblk, 256>>>(0, b1);

    // layer 2
    k_gemm<<<nblk, 256, GEMM_SMEM>>>(0, g1, be1, W2);
    k_gather<<<gblk, 256>>>(1, b2);

    // layer 3
    k_gemm<<<nblk, 256, GEMM_SMEM>>>(1, g2, be2, W3);
    k_gather<<<gblk, 256>>>(2, b3);

    // pooling + classifier
    k_pool<<<nblk, 128>>>(batch, g3, be3);
    k_fc<<<Gg, 128>>>(fcW, fcb, out);
}

// round 7
// speedup vs baseline: 1.4273x; 1.2569x over previous
#include <cuda_runtime.h>
#include <cuda_fp16.h>
#include <cstdint>

#define Nn 50000
#define Ee 600000
#define Gg 512
#define Hh 128
#define SCAN_BLKS ((Nn + 255) / 256)   // 196
#define EPSf 1e-5f
#define Pp 136                          // smem pitch in halfs (conflict-free)

typedef unsigned long long u64;

// ---------------- device scratch (no allocations allowed) ----------------
__device__ __align__(16) __half2 g_hwh[(size_t)Nn * 64];   // h @ W in fp16 (row = 256B)
__device__ __align__(16) float g_agg[(size_t)Nn * Hh];     // aggregated (GEMM/pool input)
__device__ __align__(16) float g_P[470 * Hh];              // projected embedding tables
__device__ __align__(16) float g_dinv[Nn];
__device__ __align__(16) float g_bnsum[3 * Hh];
__device__ __align__(16) float g_bnsq[3 * Hh];
__device__ __align__(16) float g_pooled[Gg * Hh];
__device__ __align__(16) float g_cnt[Gg];
__device__ int g_degcnt[Nn];
__device__ int g_cursor[Nn];
__device__ int g_base[Nn + 1];
__device__ int g_esrc[Ee];
__device__ int g_bsum[256];

// ---------------- warp scan helper ----------------
__device__ __forceinline__ int warp_incl_scan(int v, int lane) {
#pragma unroll
    for (int off = 1; off < 32; off <<= 1) {
        int y = __shfl_up_sync(0xFFFFFFFFu, v, off);
        if (lane >= off) v += y;
    }
    return v;
}

// ---------------- HMMA m16n8k16 fp16 -> fp32 ----------------
__device__ __forceinline__ void mma16816(float4& c, unsigned a0, unsigned a1,
                                         unsigned a2, unsigned a3,
                                         unsigned b0, unsigned b1) {
    asm volatile(
        "mma.sync.aligned.m16n8k16.row.col.f32.f16.f16.f32 "
        "{%0,%1,%2,%3}, {%4,%5,%6,%7}, {%8,%9}, {%0,%1,%2,%3};"
        : "+f"(c.x), "+f"(c.y), "+f"(c.z), "+f"(c.w)
        : "r"(a0), "r"(a1), "r"(a2), "r"(a3), "r"(b0), "r"(b1));
}

// ---------------- init: zero accumulators ----------------
__global__ void k_init() {
    int i = blockIdx.x * blockDim.x + threadIdx.x;   // 65536 threads
    if (i < Nn) { g_degcnt[i] = 0; g_cursor[i] = 0; }
    if (i < Gg * Hh) g_pooled[i] = 0.0f;
    if (i < Gg) g_cnt[i] = 0.0f;
    if (i < 3 * Hh) { g_bnsum[i] = 0.0f; g_bnsq[i] = 0.0f; }
}

// ---------------- degree count + graph-size count ----------------
__global__ void k_count(const int* __restrict__ ei, const int* __restrict__ batch) {
    int j = blockIdx.x * blockDim.x + threadIdx.x;
    if (j < Ee) atomicAdd(&g_degcnt[ei[Ee + j]], 1);
    if (j < Nn) atomicAdd(&g_cnt[batch[j]], 1.0f);
}

// ---------------- two-level exclusive scan of degcnt (warp-shuffle) ----------------
__global__ void k_scan1() {
    __shared__ int wsum[8];
    int tid = threadIdx.x;
    int lane = tid & 31, wp = tid >> 5;
    int i = blockIdx.x * 256 + tid;
    int v = (i < Nn) ? g_degcnt[i] : 0;
    int incl = warp_incl_scan(v, lane);
    if (lane == 31) wsum[wp] = incl;
    __syncthreads();
    int woff = 0;
#pragma unroll
    for (int w = 0; w < 8; w++) woff += (w < wp) ? wsum[w] : 0;
    if (i < Nn) g_base[i] = woff + incl - v;                 // exclusive
    if (tid == 255) g_bsum[blockIdx.x] = woff + incl;        // block total
}
// finalize: every block redundantly scans the 196 block sums, adds prefix, dinv
__global__ void k_scan3() {
    __shared__ int wsum[8];
    __shared__ int sex[256];
    int tid = threadIdx.x;
    int lane = tid & 31, wp = tid >> 5;
    int bv = (tid < SCAN_BLKS) ? g_bsum[tid] : 0;
    int incl = warp_incl_scan(bv, lane);
    if (lane == 31) wsum[wp] = incl;
    __syncthreads();
    int woff = 0;
#pragma unroll
    for (int w = 0; w < 8; w++) woff += (w < wp) ? wsum[w] : 0;
    sex[tid] = woff + incl - bv;                             // exclusive block offset
    __syncthreads();
    int boff = sex[blockIdx.x];
    int i = blockIdx.x * 256 + tid;
    if (i < Nn) {
        g_base[i] += boff;
        g_dinv[i] = rsqrtf((float)g_degcnt[i] + 1.0f);
    }
    if (i == 0) g_base[Nn] = Ee;
}

// ---------------- place edges into CSR-by-dst ----------------
__global__ void k_place(const int* __restrict__ ei) {
    int e = blockIdx.x * blockDim.x + threadIdx.x;
    if (e >= Ee) return;
    int dst = ei[Ee + e];
    int pos = g_base[dst] + atomicAdd(&g_cursor[dst], 1);
    g_esrc[pos] = ei[e];
}

// ---------------- project all embedding tables through W1 (one kernel) ----------------
__global__ void k_projall(const float* __restrict__ emb0, const float* __restrict__ emb1,
                          const float* __restrict__ emb2, const float* __restrict__ emb5,
                          const float* __restrict__ W1) {
    int bv = blockIdx.x;              // 0..469
    int c = threadIdx.x;
    const float* emb; int koff, v;
    if (bv < 96)       { emb = emb0; koff = 1;  v = bv; }
    else if (bv < 192) { emb = emb1; koff = 33; v = bv - 96; }
    else if (bv < 288) { emb = emb2; koff = 65; v = bv - 192; }
    else               { emb = emb5; koff = 97; v = bv - 288; }
    float acc = 0.0f;
#pragma unroll
    for (int j = 0; j < 32; j++)
        acc += emb[v * 32 + j] * W1[(koff + j) * Hh + c];
    g_P[(size_t)bv * Hh + c] = acc;
}

// ---------------- layer-1 hw (embedding lookup form), fp16 output ----------------
__global__ void k_layer1(const float* __restrict__ x, const float* __restrict__ W1) {
    int tid = threadIdx.x;
    int node = blockIdx.x * 4 + (tid >> 6);
    if (node >= Nn) return;
    int c2 = tid & 63;                // half2 index; channels 2*c2, 2*c2+1
    int c0 = c2 * 2;
    const float* xr = x + (size_t)node * 5;
    float pos = xr[0];
    int i0 = (int)xr[1], i1 = (int)xr[2], i2 = (int)xr[3], i5 = (int)xr[4];
    const float* p0 = g_P + (size_t)i0 * Hh;
    const float* p1 = g_P + (size_t)(96 + i1) * Hh;
    const float* p2 = g_P + (size_t)(192 + i2) * Hh;
    const float* p5 = g_P + (size_t)(288 + i5) * Hh;
    float va = pos * W1[c0]     + p0[c0]     + p1[c0]     + p2[c0]     + p5[c0];
    float vb = pos * W1[c0 + 1] + p0[c0 + 1] + p1[c0 + 1] + p2[c0 + 1] + p5[c0 + 1];
    g_hwh[(size_t)node * 64 + c2] = __floats2half2_rn(va, vb);
}

// ---------------- fused aggregation + self-loop + bias + BN partial stats ------
__global__ void __launch_bounds__(256) k_gather(int layer, const float* __restrict__ bias) {
    __shared__ float s_sum[8][132];
    __shared__ float s_sq[8][132];
    int tid = threadIdx.x;
    int wp = tid >> 5;
    int lane = tid & 31;
    int gw = blockIdx.x * 8 + wp;

    float4 outv = make_float4(0.f, 0.f, 0.f, 0.f);
    if (gw < Nn) {
        int s = g_base[gw], e = g_base[gw + 1];
        float di = g_dinv[gw];
        float4 acc = make_float4(0.f, 0.f, 0.f, 0.f);
        int t = s;
        for (; t + 4 <= e; t += 4) {
            int s0 = g_esrc[t + 0], s1 = g_esrc[t + 1];
            int s2 = g_esrc[t + 2], s3 = g_esrc[t + 3];
            float n0 = g_dinv[s0], n1 = g_dinv[s1];
            float n2 = g_dinv[s2], n3 = g_dinv[s3];
            uint2 r0 = *(const uint2*)(g_hwh + (size_t)s0 * 64 + lane * 2);
            uint2 r1 = *(const uint2*)(g_hwh + (size_t)s1 * 64 + lane * 2);
            uint2 r2 = *(const uint2*)(g_hwh + (size_t)s2 * 64 + lane * 2);
            uint2 r3 = *(const uint2*)(g_hwh + (size_t)s3 * 64 + lane * 2);
            float2 a0 = __half22float2(*(__half2*)&r0.x), b0 = __half22float2(*(__half2*)&r0.y);
            float2 a1 = __half22float2(*(__half2*)&r1.x), b1 = __half22float2(*(__half2*)&r1.y);
            float2 a2 = __half22float2(*(__half2*)&r2.x), b2 = __half22float2(*(__half2*)&r2.y);
            float2 a3 = __half22float2(*(__half2*)&r3.x), b3 = __half22float2(*(__half2*)&r3.y);
            acc.x += (a0.x * n0 + a1.x * n1) + (a2.x * n2 + a3.x * n3);
            acc.y += (a0.y * n0 + a1.y * n1) + (a2.y * n2 + a3.y * n3);
            acc.z += (b0.x * n0 + b1.x * n1) + (b2.x * n2 + b3.x * n3);
            acc.w += (b0.y * n0 + b1.y * n1) + (b2.y * n2 + b3.y * n3);
        }
        for (; t < e; t++) {
            int s0 = g_esrc[t];
            float n0 = g_dinv[s0];
            uint2 r0 = *(const uint2*)(g_hwh + (size_t)s0 * 64 + lane * 2);
            float2 a0 = __half22float2(*(__half2*)&r0.x), b0 = __half22float2(*(__half2*)&r0.y);
            acc.x += a0.x * n0; acc.y += a0.y * n0;
            acc.z += b0.x * n0; acc.w += b0.y * n0;
        }
        float d2 = di * di;
        uint2 rs = *(const uint2*)(g_hwh + (size_t)gw * 64 + lane * 2);
        float2 ha = __half22float2(*(__half2*)&rs.x), hb = __half22float2(*(__half2*)&rs.y);
        float4 bv = *(const float4*)(bias + lane * 4);
        outv.x = acc.x * di + ha.x * d2 + bv.x;
        outv.y = acc.y * di + ha.y * d2 + bv.y;
        outv.z = acc.z * di + hb.x * d2 + bv.z;
        outv.w = acc.w * di + hb.y * d2 + bv.w;
        *(float4*)(g_agg + (size_t)gw * Hh + lane * 4) = outv;
    }
    s_sum[wp][lane * 4 + 0] = outv.x; s_sq[wp][lane * 4 + 0] = outv.x * outv.x;
    s_sum[wp][lane * 4 + 1] = outv.y; s_sq[wp][lane * 4 + 1] = outv.y * outv.y;
    s_sum[wp][lane * 4 + 2] = outv.z; s_sq[wp][lane * 4 + 2] = outv.z * outv.z;
    s_sum[wp][lane * 4 + 3] = outv.w; s_sq[wp][lane * 4 + 3] = outv.w * outv.w;
    __syncthreads();
    if (tid < 128) {
        float s = 0.f, q = 0.f;
#pragma unroll
        for (int w = 0; w < 8; w++) { s += s_sum[w][tid]; q += s_sq[w][tid]; }
        atomicAdd(&g_bnsum[layer * Hh + tid], s);
        atomicAdd(&g_bnsq[layer * Hh + tid], q);
    }
}

// ---------------- tensor-core GEMM: relu(bn(A)) @ W -> hw (fp16) ----------------
// A tile 128x128 fp16 in smem (row-major, pitch Pp); W transposed fp16 in smem
// (Wt[n][k], pitch Pp). 8 warps, each computes a 16-row stripe x 128 cols via
// mma.sync m16n8k16 with fp32 accumulators.
#define GEMM_SMEM (2 * 128 * Pp * 2)
__global__ void __launch_bounds__(256)
k_gemm(int layer, const float* __restrict__ gamma, const float* __restrict__ beta,
       const float* __restrict__ W) {
    extern __shared__ __half smh[];
    __half* As = smh;                 // 128 x Pp
    __half* Wt = smh + 128 * Pp;      // 128 x Pp (transposed W: Wt[n][k])
    __shared__ float s_scale[128];
    __shared__ float s_shift[128];
    int tid = threadIdx.x;
    int row0 = blockIdx.x * 128;

    if (tid < 128) {
        float mean = g_bnsum[layer * Hh + tid] * (1.0f / Nn);
        float var = g_bnsq[layer * Hh + tid] * (1.0f / Nn) - mean * mean;
        float sc = gamma[tid] * rsqrtf(var + EPSf);
        s_scale[tid] = sc;
        s_shift[tid] = beta[tid] - mean * sc;
    }

    // load W transposed into Wt as fp16
    for (int t = tid; t < 128 * 32; t += 256) {
        int k = t >> 5, n0 = (t & 31) * 4;
        float4 wv = ((const float4*)W)[t];
        Wt[(n0 + 0) * Pp + k] = __float2half_rn(wv.x);
        Wt[(n0 + 1) * Pp + k] = __float2half_rn(wv.y);
        Wt[(n0 + 2) * Pp + k] = __float2half_rn(wv.z);
        Wt[(n0 + 3) * Pp + k] = __float2half_rn(wv.w);
    }
    __syncthreads();

    // load A tile with BN+ReLU, convert to fp16, zero-pad OOB rows
    for (int t = tid; t < 128 * 32; t += 256) {
        int r = t >> 5, q = t & 31;
        int grow = row0 + r;
        float4 v = make_float4(0.f, 0.f, 0.f, 0.f);
        if (grow < Nn) {
            v = ((const float4*)(g_agg + (size_t)grow * Hh))[q];
            float4 sc = ((const float4*)s_scale)[q];
            float4 sh = ((const float4*)s_shift)[q];
            v.x = fmaxf(v.x * sc.x + sh.x, 0.f);
            v.y = fmaxf(v.y * sc.y + sh.y, 0.f);
            v.z = fmaxf(v.z * sc.z + sh.z, 0.f);
            v.w = fmaxf(v.w * sc.w + sh.w, 0.f);
        }
        __half2 h0 = __floats2half2_rn(v.x, v.y);
        __half2 h1 = __floats2half2_rn(v.z, v.w);
        uint2 u = make_uint2(*(unsigned*)&h0, *(unsigned*)&h1);
        *(uint2*)(As + r * Pp + q * 4) = u;
    }
    __syncthreads();

    int wp = tid >> 5;        // warp 0..7 -> rows wp*16 .. +15
    int lane = tid & 31;
    int g = lane >> 2;        // groupID 0..7
    int tg = lane & 3;        // threadID_in_group 0..3

    float4 c[16];
#pragma unroll
    for (int nt = 0; nt < 16; nt++) c[nt] = make_float4(0.f, 0.f, 0.f, 0.f);

    const __half* Abase = As + (wp * 16 + g) * Pp + 2 * tg;
#pragma unroll
    for (int kk = 0; kk < 8; kk++) {
        const __half* Ar = Abase + kk * 16;
        unsigned a0 = *(const unsigned*)(Ar);
        unsigned a1 = *(const unsigned*)(Ar + 8 * Pp);
        unsigned a2 = *(const unsigned*)(Ar + 8);
        unsigned a3 = *(const unsigned*)(Ar + 8 * Pp + 8);
        const __half* Bb = Wt + g * Pp + kk * 16 + 2 * tg;
#pragma unroll
        for (int nt = 0; nt < 16; nt++) {
            const __half* Br = Bb + nt * 8 * Pp;
            unsigned b0 = *(const unsigned*)(Br);
            unsigned b1 = *(const unsigned*)(Br + 8);
            mma16816(c[nt], a0, a1, a2, a3, b0, b1);
        }
    }

    // epilogue: fp16 half2 stores. lane covers rows (g, g+8), cols 2tg..+1 per n-tile
    int r_lo = row0 + wp * 16 + g;
    int r_hi = r_lo + 8;
    bool ok_lo = (r_lo < Nn), ok_hi = (r_hi < Nn);
    __half2* out_lo = g_hwh + (size_t)r_lo * 64 + tg;
    __half2* out_hi = g_hwh + (size_t)r_hi * 64 + tg;
#pragma unroll
    for (int nt = 0; nt < 16; nt++) {
        if (ok_lo) out_lo[nt * 4] = __floats2half2_rn(c[nt].x, c[nt].y);
        if (ok_hi) out_hi[nt * 4] = __floats2half2_rn(c[nt].z, c[nt].w);
    }
}

// ---------------- pooling: batch is sorted -> run-length accumulate ----------------
__global__ void k_pool(const int* __restrict__ batch,
                       const float* __restrict__ gamma, const float* __restrict__ beta) {
    __shared__ int sb[128];
    int c = threadIdx.x;
    int r0 = blockIdx.x * 128;
    int nrows = min(128, Nn - r0);
    if (c < nrows) sb[c] = batch[r0 + c];
    float mean = g_bnsum[2 * Hh + c] * (1.0f / Nn);
    float var = g_bnsq[2 * Hh + c] * (1.0f / Nn) - mean * mean;
    float sc = gamma[c] * rsqrtf(var + EPSf);
    float sh = beta[c] - mean * sc;
    __syncthreads();
    float acc = 0.f;
    int cur = sb[0];
    for (int r = 0; r < nrows; r++) {
        int gr = sb[r];
        if (gr != cur) { atomicAdd(&g_pooled[cur * Hh + c], acc); acc = 0.f; cur = gr; }
        float v = g_agg[(size_t)(r0 + r) * Hh + c];
        acc += fmaxf(v * sc + sh, 0.f);
    }
    atomicAdd(&g_pooled[cur * Hh + c], acc);
}

// ---------------- final FC: (pooled / cnt) @ fcW + fcb ----------------
__global__ void k_fc(const float* __restrict__ fcW, const float* __restrict__ fcb,
                     float* __restrict__ out) {
    int g = blockIdx.x, c = threadIdx.x;
    float v = g_pooled[g * Hh + c] / fmaxf(g_cnt[g], 1.0f);
    __shared__ float s0[128], s1[128], s2[128];
    s0[c] = v * fcW[c * 3 + 0];
    s1[c] = v * fcW[c * 3 + 1];
    s2[c] = v * fcW[c * 3 + 2];
    __syncthreads();
    for (int off = 64; off > 0; off >>= 1) {
        if (c < off) { s0[c] += s0[c + off]; s1[c] += s1[c + off]; s2[c] += s2[c + off]; }
        __syncthreads();
    }
    if (c == 0) {
        out[g * 3 + 0] = s0[0] + fcb[0];
        out[g * 3 + 1] = s1[0] + fcb[1];
        out[g * 3 + 2] = s2[0] + fcb[2];
    }
}

// ---------------- launch ----------------
extern "C" void kernel_launch(void* const* d_in, const int* in_sizes, int n_in,
                              void* d_out, int out_size) {
    const float* x     = (const float*)d_in[0];
    const int*   ei    = (const int*)  d_in[1];
    const int*   batch = (const int*)  d_in[2];
    const float* emb0  = (const float*)d_in[3];
    const float* emb1  = (const float*)d_in[4];
    const float* emb2  = (const float*)d_in[5];
    const float* emb5  = (const float*)d_in[6];
    const float* W1    = (const float*)d_in[7];
    const float* b1    = (const float*)d_in[8];
    const float* W2    = (const float*)d_in[9];
    const float* b2    = (const float*)d_in[10];
    const float* W3    = (const float*)d_in[11];
    const float* b3    = (const float*)d_in[12];
    const float* g1    = (const float*)d_in[13];
    const float* be1   = (const float*)d_in[14];
    const float* g2    = (const float*)d_in[15];
    const float* be2   = (const float*)d_in[16];
    const float* g3    = (const float*)d_in[17];
    const float* be3   = (const float*)d_in[18];
    const float* fcW   = (const float*)d_in[19];
    const float* fcb   = (const float*)d_in[20];
    float* out = (float*)d_out;

    cudaFuncSetAttribute(k_gemm, cudaFuncAttributeMaxDynamicSharedMemorySize, GEMM_SMEM);

    const int nblk = (Nn + 127) / 128;          // 391
    const int eblk = (Ee + 255) / 256;          // 2344
    const int gblk = (Nn + 7) / 8;              // gather blocks (8 warps = 8 nodes)

    // graph preprocessing
    k_init<<<256, 256>>>();
    k_count<<<eblk, 256>>>(ei, batch);
    k_scan1<<<SCAN_BLKS, 256>>>();
    k_scan3<<<SCAN_BLKS, 256>>>();
    k_place<<<eblk, 256>>>(ei);

    // layer 1 (embedding-decomposed GEMM)
    k_projall<<<470, 128>>>(emb0, emb1, emb2, emb5, W1);
    k_layer1<<<(Nn + 3) / 4, 256>>>(x, W1);
    k_gather<<<gblk, 256>>>(0, b1);

    // layer 2
    k_gemm<<<nblk, 256, GEMM_SMEM>>>(0, g1, be1, W2);
    k_gather<<<gblk, 256>>>(1, b2);

    // layer 3
    k_gemm<<<nblk, 256, GEMM_SMEM>>>(1, g2, be2, W3);
    k_gather<<<gblk, 256>>>(2, b3);

    // pooling + classifier
    k_pool<<<nblk, 128>>>(batch, g3, be3);
    k_fc<<<Gg, 128>>>(fcW, fcb, out);
}

// round 8
// speedup vs baseline: 1.4275x; 1.0001x over previous
#include <cuda_runtime.h>
#include <cuda_fp16.h>
#include <cstdint>

#define Nn 50000
#define Ee 600000
#define Gg 512
#define Hh 128
#define SCAN_BLKS ((Nn + 255) / 256)   // 196
#define EPSf 1e-5f
#define Pp 136                          // smem pitch in halfs (conflict-free)

typedef unsigned long long u64;

// ---------------- device scratch (no allocations allowed) ----------------
// g_hwh holds (h @ W) * dinv[row]  in fp16 (row = 256B)
__device__ __align__(16) __half2 g_hwh[(size_t)Nn * 64];
__device__ __align__(16) float g_agg[(size_t)Nn * Hh];     // aggregated (GEMM/pool input)
__device__ __align__(16) float g_P[470 * Hh];              // projected embedding tables
__device__ __align__(16) float g_dinv[Nn];
__device__ __align__(16) float g_bnsum[3 * Hh];
__device__ __align__(16) float g_bnsq[3 * Hh];
__device__ __align__(16) float g_pooled[Gg * Hh];
__device__ __align__(16) float g_cnt[Gg];
__device__ int g_degcnt[Nn];
__device__ int g_cursor[Nn];
__device__ int g_base[Nn + 1];
__device__ int g_esrc[Ee];
__device__ int g_bsum[256];

// ---------------- warp scan helper ----------------
__device__ __forceinline__ int warp_incl_scan(int v, int lane) {
#pragma unroll
    for (int off = 1; off < 32; off <<= 1) {
        int y = __shfl_up_sync(0xFFFFFFFFu, v, off);
        if (lane >= off) v += y;
    }
    return v;
}

// ---------------- HMMA m16n8k16 fp16 -> fp32 ----------------
__device__ __forceinline__ void mma16816(float4& c, unsigned a0, unsigned a1,
                                         unsigned a2, unsigned a3,
                                         unsigned b0, unsigned b1) {
    asm volatile(
        "mma.sync.aligned.m16n8k16.row.col.f32.f16.f16.f32 "
        "{%0,%1,%2,%3}, {%4,%5,%6,%7}, {%8,%9}, {%0,%1,%2,%3};"
        : "+f"(c.x), "+f"(c.y), "+f"(c.z), "+f"(c.w)
        : "r"(a0), "r"(a1), "r"(a2), "r"(a3), "r"(b0), "r"(b1));
}

// ---------------- init: zero accumulators ----------------
__global__ void k_init() {
    int i = blockIdx.x * blockDim.x + threadIdx.x;   // 65536 threads
    if (i < Nn) { g_degcnt[i] = 0; g_cursor[i] = 0; }
    if (i < Gg * Hh) g_pooled[i] = 0.0f;
    if (i < Gg) g_cnt[i] = 0.0f;
    if (i < 3 * Hh) { g_bnsum[i] = 0.0f; g_bnsq[i] = 0.0f; }
}

// ---------------- degree count + graph-size count (int4 vectorized) ----------------
__global__ void k_count(const int* __restrict__ ei, const int* __restrict__ batch) {
    int j = blockIdx.x * blockDim.x + threadIdx.x;
    if (j < Ee / 4) {
        int4 d = ((const int4*)(ei + Ee))[j];
        atomicAdd(&g_degcnt[d.x], 1);
        atomicAdd(&g_degcnt[d.y], 1);
        atomicAdd(&g_degcnt[d.z], 1);
        atomicAdd(&g_degcnt[d.w], 1);
    }
    if (j < Nn / 4) {
        int4 b = ((const int4*)batch)[j];
        atomicAdd(&g_cnt[b.x], 1.0f);
        atomicAdd(&g_cnt[b.y], 1.0f);
        atomicAdd(&g_cnt[b.z], 1.0f);
        atomicAdd(&g_cnt[b.w], 1.0f);
    }
}

// ---------------- two-level exclusive scan of degcnt (warp-shuffle) ----------------
__global__ void k_scan1() {
    __shared__ int wsum[8];
    int tid = threadIdx.x;
    int lane = tid & 31, wp = tid >> 5;
    int i = blockIdx.x * 256 + tid;
    int v = (i < Nn) ? g_degcnt[i] : 0;
    int incl = warp_incl_scan(v, lane);
    if (lane == 31) wsum[wp] = incl;
    __syncthreads();
    int woff = 0;
#pragma unroll
    for (int w = 0; w < 8; w++) woff += (w < wp) ? wsum[w] : 0;
    if (i < Nn) g_base[i] = woff + incl - v;                 // exclusive
    if (tid == 255) g_bsum[blockIdx.x] = woff + incl;        // block total
}
// finalize: every block redundantly scans the 196 block sums, adds prefix, dinv
__global__ void k_scan3() {
    __shared__ int wsum[8];
    __shared__ int sex[256];
    int tid = threadIdx.x;
    int lane = tid & 31, wp = tid >> 5;
    int bv = (tid < SCAN_BLKS) ? g_bsum[tid] : 0;
    int incl = warp_incl_scan(bv, lane);
    if (lane == 31) wsum[wp] = incl;
    __syncthreads();
    int woff = 0;
#pragma unroll
    for (int w = 0; w < 8; w++) woff += (w < wp) ? wsum[w] : 0;
    sex[tid] = woff + incl - bv;                             // exclusive block offset
    __syncthreads();
    int boff = sex[blockIdx.x];
    int i = blockIdx.x * 256 + tid;
    if (i < Nn) {
        g_base[i] += boff;
        g_dinv[i] = rsqrtf((float)g_degcnt[i] + 1.0f);
    }
    if (i == 0) g_base[Nn] = Ee;
}

// ---------------- place edges into CSR-by-dst (int4 vectorized) ----------------
__global__ void k_place(const int* __restrict__ ei) {
    int j = blockIdx.x * blockDim.x + threadIdx.x;
    if (j >= Ee / 4) return;
    int4 s = ((const int4*)ei)[j];
    int4 d = ((const int4*)(ei + Ee))[j];
    g_esrc[g_base[d.x] + atomicAdd(&g_cursor[d.x], 1)] = s.x;
    g_esrc[g_base[d.y] + atomicAdd(&g_cursor[d.y], 1)] = s.y;
    g_esrc[g_base[d.z] + atomicAdd(&g_cursor[d.z], 1)] = s.z;
    g_esrc[g_base[d.w] + atomicAdd(&g_cursor[d.w], 1)] = s.w;
}

// ---------------- project all embedding tables through W1 (one kernel) ----------------
__global__ void k_projall(const float* __restrict__ emb0, const float* __restrict__ emb1,
                          const float* __restrict__ emb2, const float* __restrict__ emb5,
                          const float* __restrict__ W1) {
    int bv = blockIdx.x;              // 0..469
    int c = threadIdx.x;
    const float* emb; int koff, v;
    if (bv < 96)       { emb = emb0; koff = 1;  v = bv; }
    else if (bv < 192) { emb = emb1; koff = 33; v = bv - 96; }
    else if (bv < 288) { emb = emb2; koff = 65; v = bv - 192; }
    else               { emb = emb5; koff = 97; v = bv - 288; }
    float acc = 0.0f;
#pragma unroll
    for (int j = 0; j < 32; j++)
        acc += emb[v * 32 + j] * W1[(koff + j) * Hh + c];
    g_P[(size_t)bv * Hh + c] = acc;
}

// ---------------- layer-1 hw (embedding lookup form), pre-scaled fp16 output ----------------
__global__ void k_layer1(const float* __restrict__ x, const float* __restrict__ W1) {
    int tid = threadIdx.x;
    int node = blockIdx.x * 4 + (tid >> 6);
    if (node >= Nn) return;
    int c2 = tid & 63;                // half2 index; channels 2*c2, 2*c2+1
    int c0 = c2 * 2;
    const float* xr = x + (size_t)node * 5;
    float pos = xr[0];
    int i0 = (int)xr[1], i1 = (int)xr[2], i2 = (int)xr[3], i5 = (int)xr[4];
    const float* p0 = g_P + (size_t)i0 * Hh;
    const float* p1 = g_P + (size_t)(96 + i1) * Hh;
    const float* p2 = g_P + (size_t)(192 + i2) * Hh;
    const float* p5 = g_P + (size_t)(288 + i5) * Hh;
    float di = g_dinv[node];
    float va = (pos * W1[c0]     + p0[c0]     + p1[c0]     + p2[c0]     + p5[c0]) * di;
    float vb = (pos * W1[c0 + 1] + p0[c0 + 1] + p1[c0 + 1] + p2[c0 + 1] + p5[c0 + 1]) * di;
    g_hwh[(size_t)node * 64 + c2] = __floats2half2_rn(va, vb);
}

// ---------------- fused aggregation + self-loop + bias + BN partial stats ------
// rows are pre-scaled by dinv[src]; inner loop is pure load+add, unroll x8.
// agg = dinv[dst] * (sum_src scaled_row + scaled_row[dst]) + bias
__global__ void __launch_bounds__(256) k_gather(int layer, const float* __restrict__ bias) {
    __shared__ float s_sum[8][132];
    __shared__ float s_sq[8][132];
    int tid = threadIdx.x;
    int wp = tid >> 5;
    int lane = tid & 31;
    int gw = blockIdx.x * 8 + wp;

    float4 outv = make_float4(0.f, 0.f, 0.f, 0.f);
    if (gw < Nn) {
        int s = g_base[gw], e = g_base[gw + 1];
        float di = g_dinv[gw];
        float4 accA = make_float4(0.f, 0.f, 0.f, 0.f);
        float4 accB = make_float4(0.f, 0.f, 0.f, 0.f);
        int t = s;
        for (; t + 8 <= e; t += 8) {
            int s0 = g_esrc[t + 0], s1 = g_esrc[t + 1];
            int s2 = g_esrc[t + 2], s3 = g_esrc[t + 3];
            int s4 = g_esrc[t + 4], s5 = g_esrc[t + 5];
            int s6 = g_esrc[t + 6], s7 = g_esrc[t + 7];
            uint2 r0 = *(const uint2*)(g_hwh + (size_t)s0 * 64 + lane * 2);
            uint2 r1 = *(const uint2*)(g_hwh + (size_t)s1 * 64 + lane * 2);
            uint2 r2 = *(const uint2*)(g_hwh + (size_t)s2 * 64 + lane * 2);
            uint2 r3 = *(const uint2*)(g_hwh + (size_t)s3 * 64 + lane * 2);
            uint2 r4 = *(const uint2*)(g_hwh + (size_t)s4 * 64 + lane * 2);
            uint2 r5 = *(const uint2*)(g_hwh + (size_t)s5 * 64 + lane * 2);
            uint2 r6 = *(const uint2*)(g_hwh + (size_t)s6 * 64 + lane * 2);
            uint2 r7 = *(const uint2*)(g_hwh + (size_t)s7 * 64 + lane * 2);
            float2 a0 = __half22float2(*(__half2*)&r0.x), b0 = __half22float2(*(__half2*)&r0.y);
            float2 a1 = __half22float2(*(__half2*)&r1.x), b1 = __half22float2(*(__half2*)&r1.y);
            float2 a2 = __half22float2(*(__half2*)&r2.x), b2 = __half22float2(*(__half2*)&r2.y);
            float2 a3 = __half22float2(*(__half2*)&r3.x), b3 = __half22float2(*(__half2*)&r3.y);
            float2 a4 = __half22float2(*(__half2*)&r4.x), b4 = __half22float2(*(__half2*)&r4.y);
            float2 a5 = __half22float2(*(__half2*)&r5.x), b5 = __half22float2(*(__half2*)&r5.y);
            float2 a6 = __half22float2(*(__half2*)&r6.x), b6 = __half22float2(*(__half2*)&r6.y);
            float2 a7 = __half22float2(*(__half2*)&r7.x), b7 = __half22float2(*(__half2*)&r7.y);
            accA.x += (a0.x + a1.x) + (a2.x + a3.x);
            accA.y += (a0.y + a1.y) + (a2.y + a3.y);
            accA.z += (b0.x + b1.x) + (b2.x + b3.x);
            accA.w += (b0.y + b1.y) + (b2.y + b3.y);
            accB.x += (a4.x + a5.x) + (a6.x + a7.x);
            accB.y += (a4.y + a5.y) + (a6.y + a7.y);
            accB.z += (b4.x + b5.x) + (b6.x + b7.x);
            accB.w += (b4.y + b5.y) + (b6.y + b7.y);
        }
        for (; t < e; t++) {
            int s0 = g_esrc[t];
            uint2 r0 = *(const uint2*)(g_hwh + (size_t)s0 * 64 + lane * 2);
            float2 a0 = __half22float2(*(__half2*)&r0.x), b0 = __half22float2(*(__half2*)&r0.y);
            accA.x += a0.x; accA.y += a0.y;
            accA.z += b0.x; accA.w += b0.y;
        }
        // self row (already scaled by dinv[gw])
        uint2 rs = *(const uint2*)(g_hwh + (size_t)gw * 64 + lane * 2);
        float2 ha = __half22float2(*(__half2*)&rs.x), hb = __half22float2(*(__half2*)&rs.y);
        accA.x += ha.x + accB.x; accA.y += ha.y + accB.y;
        accA.z += hb.x + accB.z; accA.w += hb.y + accB.w;
        float4 bv = *(const float4*)(bias + lane * 4);
        outv.x = accA.x * di + bv.x;
        outv.y = accA.y * di + bv.y;
        outv.z = accA.z * di + bv.z;
        outv.w = accA.w * di + bv.w;
        *(float4*)(g_agg + (size_t)gw * Hh + lane * 4) = outv;
    }
    s_sum[wp][lane * 4 + 0] = outv.x; s_sq[wp][lane * 4 + 0] = outv.x * outv.x;
    s_sum[wp][lane * 4 + 1] = outv.y; s_sq[wp][lane * 4 + 1] = outv.y * outv.y;
    s_sum[wp][lane * 4 + 2] = outv.z; s_sq[wp][lane * 4 + 2] = outv.z * outv.z;
    s_sum[wp][lane * 4 + 3] = outv.w; s_sq[wp][lane * 4 + 3] = outv.w * outv.w;
    __syncthreads();
    if (tid < 128) {
        float s = 0.f, q = 0.f;
#pragma unroll
        for (int w = 0; w < 8; w++) { s += s_sum[w][tid]; q += s_sq[w][tid]; }
        atomicAdd(&g_bnsum[layer * Hh + tid], s);
        atomicAdd(&g_bnsq[layer * Hh + tid], q);
    }
}

// ---------------- tensor-core GEMM: relu(bn(A)) @ W -> hw (pre-scaled fp16) ----------------
#define GEMM_SMEM (2 * 128 * Pp * 2)
__global__ void __launch_bounds__(256)
k_gemm(int layer, const float* __restrict__ gamma, const float* __restrict__ beta,
       const float* __restrict__ W) {
    extern __shared__ __half smh[];
    __half* As = smh;                 // 128 x Pp
    __half* Wt = smh + 128 * Pp;      // 128 x Pp (transposed W: Wt[n][k])
    __shared__ float s_scale[128];
    __shared__ float s_shift[128];
    int tid = threadIdx.x;
    int row0 = blockIdx.x * 128;

    if (tid < 128) {
        float mean = g_bnsum[layer * Hh + tid] * (1.0f / Nn);
        float var = g_bnsq[layer * Hh + tid] * (1.0f / Nn) - mean * mean;
        float sc = gamma[tid] * rsqrtf(var + EPSf);
        s_scale[tid] = sc;
        s_shift[tid] = beta[tid] - mean * sc;
    }

    // load W transposed into Wt as fp16
    for (int t = tid; t < 128 * 32; t += 256) {
        int k = t >> 5, n0 = (t & 31) * 4;
        float4 wv = ((const float4*)W)[t];
        Wt[(n0 + 0) * Pp + k] = __float2half_rn(wv.x);
        Wt[(n0 + 1) * Pp + k] = __float2half_rn(wv.y);
        Wt[(n0 + 2) * Pp + k] = __float2half_rn(wv.z);
        Wt[(n0 + 3) * Pp + k] = __float2half_rn(wv.w);
    }
    __syncthreads();

    // load A tile with BN+ReLU, convert to fp16, zero-pad OOB rows
    for (int t = tid; t < 128 * 32; t += 256) {
        int r = t >> 5, q = t & 31;
        int grow = row0 + r;
        float4 v = make_float4(0.f, 0.f, 0.f, 0.f);
        if (grow < Nn) {
            v = ((const float4*)(g_agg + (size_t)grow * Hh))[q];
            float4 sc = ((const float4*)s_scale)[q];
            float4 sh = ((const float4*)s_shift)[q];
            v.x = fmaxf(v.x * sc.x + sh.x, 0.f);
            v.y = fmaxf(v.y * sc.y + sh.y, 0.f);
            v.z = fmaxf(v.z * sc.z + sh.z, 0.f);
            v.w = fmaxf(v.w * sc.w + sh.w, 0.f);
        }
        __half2 h0 = __floats2half2_rn(v.x, v.y);
        __half2 h1 = __floats2half2_rn(v.z, v.w);
        uint2 u = make_uint2(*(unsigned*)&h0, *(unsigned*)&h1);
        *(uint2*)(As + r * Pp + q * 4) = u;
    }
    __syncthreads();

    int wp = tid >> 5;        // warp 0..7 -> rows wp*16 .. +15
    int lane = tid & 31;
    int g = lane >> 2;        // groupID 0..7
    int tg = lane & 3;        // threadID_in_group 0..3

    float4 c[16];
#pragma unroll
    for (int nt = 0; nt < 16; nt++) c[nt] = make_float4(0.f, 0.f, 0.f, 0.f);

    const __half* Abase = As + (wp * 16 + g) * Pp + 2 * tg;
#pragma unroll
    for (int kk = 0; kk < 8; kk++) {
        const __half* Ar = Abase + kk * 16;
        unsigned a0 = *(const unsigned*)(Ar);
        unsigned a1 = *(const unsigned*)(Ar + 8 * Pp);
        unsigned a2 = *(const unsigned*)(Ar + 8);
        unsigned a3 = *(const unsigned*)(Ar + 8 * Pp + 8);
        const __half* Bb = Wt + g * Pp + kk * 16 + 2 * tg;
#pragma unroll
        for (int nt = 0; nt < 16; nt++) {
            const __half* Br = Bb + nt * 8 * Pp;
            unsigned b0 = *(const unsigned*)(Br);
            unsigned b1 = *(const unsigned*)(Br + 8);
            mma16816(c[nt], a0, a1, a2, a3, b0, b1);
        }
    }

    // epilogue: pre-scale by dinv[row], fp16 half2 stores
    int r_lo = row0 + wp * 16 + g;
    int r_hi = r_lo + 8;
    bool ok_lo = (r_lo < Nn), ok_hi = (r_hi < Nn);
    float d_lo = ok_lo ? g_dinv[r_lo] : 0.f;
    float d_hi = ok_hi ? g_dinv[r_hi] : 0.f;
    __half2* out_lo = g_hwh + (size_t)r_lo * 64 + tg;
    __half2* out_hi = g_hwh + (size_t)r_hi * 64 + tg;
#pragma unroll
    for (int nt = 0; nt < 16; nt++) {
        if (ok_lo) out_lo[nt * 4] = __floats2half2_rn(c[nt].x * d_lo, c[nt].y * d_lo);
        if (ok_hi) out_hi[nt * 4] = __floats2half2_rn(c[nt].z * d_hi, c[nt].w * d_hi);
    }
}

// ---------------- pooling: batch is sorted -> run-length accumulate ----------------
__global__ void k_pool(const int* __restrict__ batch,
                       const float* __restrict__ gamma, const float* __restrict__ beta) {
    __shared__ int sb[128];
    int c = threadIdx.x;
    int r0 = blockIdx.x * 128;
    int nrows = min(128, Nn - r0);
    if (c < nrows) sb[c] = batch[r0 + c];
    float mean = g_bnsum[2 * Hh + c] * (1.0f / Nn);
    float var = g_bnsq[2 * Hh + c] * (1.0f / Nn) - mean * mean;
    float sc = gamma[c] * rsqrtf(var + EPSf);
    float sh = beta[c] - mean * sc;
    __syncthreads();
    float acc = 0.f;
    int cur = sb[0];
    for (int r = 0; r < nrows; r++) {
        int gr = sb[r];
        if (gr != cur) { atomicAdd(&g_pooled[cur * Hh + c], acc); acc = 0.f; cur = gr; }
        float v = g_agg[(size_t)(r0 + r) * Hh + c];
        acc += fmaxf(v * sc + sh, 0.f);
    }
    atomicAdd(&g_pooled[cur * Hh + c], acc);
}

// ---------------- final FC: (pooled / cnt) @ fcW + fcb ----------------
__global__ void k_fc(const float* __restrict__ fcW, const float* __restrict__ fcb,
                     float* __restrict__ out) {
    int g = blockIdx.x, c = threadIdx.x;
    float v = g_pooled[g * Hh + c] / fmaxf(g_cnt[g], 1.0f);
    __shared__ float s0[128], s1[128], s2[128];
    s0[c] = v * fcW[c * 3 + 0];
    s1[c] = v * fcW[c * 3 + 1];
    s2[c] = v * fcW[c * 3 + 2];
    __syncthreads();
    for (int off = 64; off > 0; off >>= 1) {
        if (c < off) { s0[c] += s0[c + off]; s1[c] += s1[c + off]; s2[c] += s2[c + off]; }
        __syncthreads();
    }
    if (c == 0) {
        out[g * 3 + 0] = s0[0] + fcb[0];
        out[g * 3 + 1] = s1[0] + fcb[1];
        out[g * 3 + 2] = s2[0] + fcb[2];
    }
}

// ---------------- launch ----------------
extern "C" void kernel_launch(void* const* d_in, const int* in_sizes, int n_in,
                              void* d_out, int out_size) {
    const float* x     = (const float*)d_in[0];
    const int*   ei    = (const int*)  d_in[1];
    const int*   batch = (const int*)  d_in[2];
    const float* emb0  = (const float*)d_in[3];
    const float* emb1  = (const float*)d_in[4];
    const float* emb2  = (const float*)d_in[5];
    const float* emb5  = (const float*)d_in[6];
    const float* W1    = (const float*)d_in[7];
    const float* b1    = (const float*)d_in[8];
    const float* W2    = (const float*)d_in[9];
    const float* b2    = (const float*)d_in[10];
    const float* W3    = (const float*)d_in[11];
    const float* b3    = (const float*)d_in[12];
    const float* g1    = (const float*)d_in[13];
    const float* be1   = (const float*)d_in[14];
    const float* g2    = (const float*)d_in[15];
    const float* be2   = (const float*)d_in[16];
    const float* g3    = (const float*)d_in[17];
    const float* be3   = (const float*)d_in[18];
    const float* fcW   = (const float*)d_in[19];
    const float* fcb   = (const float*)d_in[20];
    float* out = (float*)d_out;

    cudaFuncSetAttribute(k_gemm, cudaFuncAttributeMaxDynamicSharedMemorySize, GEMM_SMEM);

    const int nblk = (Nn + 127) / 128;          // 391
    const int e4blk = (Ee / 4 + 255) / 256;     // 586
    const int gblk = (Nn + 7) / 8;              // gather blocks (8 warps = 8 nodes)

    // graph preprocessing
    k_init<<<256, 256>>>();
    k_count<<<e4blk, 256>>>(ei, batch);
    k_scan1<<<SCAN_BLKS, 256>>>();
    k_scan3<<<SCAN_BLKS, 256>>>();
    k_place<<<e4blk, 256>>>(ei);

    // layer 1 (embedding-decomposed GEMM); k_layer1 needs dinv -> after scan3
    k_projall<<<470, 128>>>(emb0, emb1, emb2, emb5, W1);
    k_layer1<<<(Nn + 3) / 4, 256>>>(x, W1);
    k_gather<<<gblk, 256>>>(0, b1);

    // layer 2
    k_gemm<<<nblk, 256, GEMM_SMEM>>>(0, g1, be1, W2);
    k_gather<<<gblk, 256>>>(1, b2);

    // layer 3
    k_gemm<<<nblk, 256, GEMM_SMEM>>>(1, g2, be2, W3);
    k_gather<<<gblk, 256>>>(2, b3);

    // pooling + classifier
    k_pool<<<nblk, 128>>>(batch, g3, be3);
    k_fc<<<Gg, 128>>>(fcW, fcb, out);
}

// round 9
// speedup vs baseline: 1.4850x; 1.0403x over previous
#include <cuda_runtime.h>
#include <cuda_fp16.h>
#include <cstdint>

#define Nn 50000
#define Ee 600000
#define Gg 512
#define Hh 128
#define SCAN_BLKS ((Nn + 255) / 256)   // 196
#define PROJ_BLKS 235                   // ceil(470/2), 2 table rows per 256-thr block
#define E4BLK ((Ee / 4 + 255) / 256)    // 586
#define L1BLK ((Nn + 3) / 4)            // 12500
#define EPSf 1e-5f
#define Pp 136                          // smem pitch in halfs (conflict-free)

typedef unsigned long long u64;

// ---------------- device scratch (no allocations allowed) ----------------
// g_hwh holds (h @ W) * dinv[row]  in fp16 (row = 256B)
__device__ __align__(16) __half2 g_hwh[(size_t)Nn * 64];
__device__ __align__(16) float g_agg[(size_t)Nn * Hh];     // aggregated (GEMM/pool input)
__device__ __align__(16) float g_P[470 * Hh];              // projected embedding tables
__device__ __align__(16) float g_dinv[Nn];
__device__ __align__(16) float g_bnsum[3 * Hh];
__device__ __align__(16) float g_bnsq[3 * Hh];
__device__ __align__(16) float g_pooled[Gg * Hh];
__device__ __align__(16) float g_cnt[Gg];
__device__ int g_degcnt[Nn];
__device__ int g_cursor[Nn];
__device__ int g_base[Nn + 1];
__device__ int g_esrc[Ee];
__device__ int g_sflag[SCAN_BLKS];     // lookback flags: (aggregate<<1)|1

// NOTE: all per-replay zeroing of g_degcnt/g_cursor/g_bnsum/g_bnsq/g_sflag/
// g_pooled/g_cnt happens at the TAIL of the graph (k_fc). First execution
// relies on CUDA zero-initialization of __device__ globals.

// ---------------- warp scan helper ----------------
__device__ __forceinline__ int warp_incl_scan(int v, int lane) {
#pragma unroll
    for (int off = 1; off < 32; off <<= 1) {
        int y = __shfl_up_sync(0xFFFFFFFFu, v, off);
        if (lane >= off) v += y;
    }
    return v;
}

// ---------------- HMMA m16n8k16 fp16 -> fp32 ----------------
__device__ __forceinline__ void mma16816(float4& c, unsigned a0, unsigned a1,
                                         unsigned a2, unsigned a3,
                                         unsigned b0, unsigned b1) {
    asm volatile(
        "mma.sync.aligned.m16n8k16.row.col.f32.f16.f16.f32 "
        "{%0,%1,%2,%3}, {%4,%5,%6,%7}, {%8,%9}, {%0,%1,%2,%3};"
        : "+f"(c.x), "+f"(c.y), "+f"(c.z), "+f"(c.w)
        : "r"(a0), "r"(a1), "r"(a2), "r"(a3), "r"(b0), "r"(b1));
}

// ---------------- degree count + graph-size count (int4 vectorized) ----------------
__global__ void k_count(const int* __restrict__ ei, const int* __restrict__ batch) {
    int j = blockIdx.x * blockDim.x + threadIdx.x;
    if (j < Ee / 4) {
        int4 d = ((const int4*)(ei + Ee))[j];
        atomicAdd(&g_degcnt[d.x], 1);
        atomicAdd(&g_degcnt[d.y], 1);
        atomicAdd(&g_degcnt[d.z], 1);
        atomicAdd(&g_degcnt[d.w], 1);
    }
    if (j < Nn / 4) {
        int4 b = ((const int4*)batch)[j];
        atomicAdd(&g_cnt[b.x], 1.0f);
        atomicAdd(&g_cnt[b.y], 1.0f);
        atomicAdd(&g_cnt[b.z], 1.0f);
        atomicAdd(&g_cnt[b.w], 1.0f);
    }
}

// ---------------- fused: decoupled-lookback scan (blocks 0..195) + W1-projection
// of embedding tables (blocks 196..430). Single kernel replaces scan1+scan3+projall.
__global__ void __launch_bounds__(256) k_scan_proj(
    const float* __restrict__ emb0, const float* __restrict__ emb1,
    const float* __restrict__ emb2, const float* __restrict__ emb5,
    const float* __restrict__ W1) {
    int bid = blockIdx.x;
    int tid = threadIdx.x;

    if (bid >= SCAN_BLKS) {
        // ---- projection part: 2 table rows per block ----
        int idx = (bid - SCAN_BLKS) * 2 + (tid >> 7);
        if (idx >= 470) return;
        int c = tid & 127;
        const float* emb; int koff, v;
        if (idx < 96)       { emb = emb0; koff = 1;  v = idx; }
        else if (idx < 192) { emb = emb1; koff = 33; v = idx - 96; }
        else if (idx < 288) { emb = emb2; koff = 65; v = idx - 192; }
        else                { emb = emb5; koff = 97; v = idx - 288; }
        float acc = 0.0f;
#pragma unroll
        for (int j = 0; j < 32; j++)
            acc += emb[v * 32 + j] * W1[(koff + j) * Hh + c];
        g_P[(size_t)idx * Hh + c] = acc;
        return;
    }

    // ---- scan part ----
    __shared__ int wsum[8];
    __shared__ int wred[8];
    int lane = tid & 31, wp = tid >> 5;
    int i = bid * 256 + tid;
    int v = (i < Nn) ? g_degcnt[i] : 0;
    int incl = warp_incl_scan(v, lane);
    if (lane == 31) wsum[wp] = incl;
    __syncthreads();
    int woff = 0, total = 0;
#pragma unroll
    for (int w = 0; w < 8; w++) {
        woff += (w < wp) ? wsum[w] : 0;
        total += wsum[w];
    }
    int excl = woff + incl - v;

    // publish (aggregate<<1)|1 ; Ee < 2^30 so it fits
    if (tid == 0) atomicExch(&g_sflag[bid], (total << 1) | 1);

    // lookback: thread t (< bid) spins for block t's aggregate
    int mysum = 0;
    if (tid < bid) {
        int f;
        do { f = atomicAdd(&g_sflag[tid], 0); } while (!(f & 1));
        mysum = f >> 1;
    }
    // block-reduce mysum -> prefix (same value in all threads)
#pragma unroll
    for (int off = 16; off > 0; off >>= 1)
        mysum += __shfl_down_sync(0xFFFFFFFFu, mysum, off);
    if (lane == 0) wred[wp] = mysum;
    __syncthreads();
    int prefix = 0;
#pragma unroll
    for (int w = 0; w < 8; w++) prefix += wred[w];

    if (i < Nn) {
        g_base[i] = excl + prefix;
        g_dinv[i] = rsqrtf((float)g_degcnt[i] + 1.0f);
    }
    if (i == 0) g_base[Nn] = Ee;
}

// ---------------- fused: CSR edge placement (blocks 0..585) + layer-1 hw
// production (blocks 586..13085). Both depend only on k_scan_proj.
__global__ void __launch_bounds__(256) k_place_layer1(
    const int* __restrict__ ei, const float* __restrict__ x,
    const float* __restrict__ W1) {
    int tid = threadIdx.x;
    if (blockIdx.x < E4BLK) {
        int j = blockIdx.x * 256 + tid;
        if (j >= Ee / 4) return;
        int4 s = ((const int4*)ei)[j];
        int4 d = ((const int4*)(ei + Ee))[j];
        g_esrc[g_base[d.x] + atomicAdd(&g_cursor[d.x], 1)] = s.x;
        g_esrc[g_base[d.y] + atomicAdd(&g_cursor[d.y], 1)] = s.y;
        g_esrc[g_base[d.z] + atomicAdd(&g_cursor[d.z], 1)] = s.z;
        g_esrc[g_base[d.w] + atomicAdd(&g_cursor[d.w], 1)] = s.w;
        return;
    }
    // layer-1: node = 4 per block, thread computes 2 channels, pre-scaled by dinv
    int node = (blockIdx.x - E4BLK) * 4 + (tid >> 6);
    if (node >= Nn) return;
    int c2 = tid & 63;
    int c0 = c2 * 2;
    const float* xr = x + (size_t)node * 5;
    float pos = xr[0];
    int i0 = (int)xr[1], i1 = (int)xr[2], i2 = (int)xr[3], i5 = (int)xr[4];
    const float* p0 = g_P + (size_t)i0 * Hh;
    const float* p1 = g_P + (size_t)(96 + i1) * Hh;
    const float* p2 = g_P + (size_t)(192 + i2) * Hh;
    const float* p5 = g_P + (size_t)(288 + i5) * Hh;
    float di = g_dinv[node];
    float va = (pos * W1[c0]     + p0[c0]     + p1[c0]     + p2[c0]     + p5[c0]) * di;
    float vb = (pos * W1[c0 + 1] + p0[c0 + 1] + p1[c0 + 1] + p2[c0 + 1] + p5[c0 + 1]) * di;
    g_hwh[(size_t)node * 64 + c2] = __floats2half2_rn(va, vb);
}

// ---------------- fused aggregation + self-loop + bias + BN partial stats ------
// rows are pre-scaled by dinv[src]; inner loop is pure load+add, unroll x8.
__global__ void __launch_bounds__(256) k_gather(int layer, const float* __restrict__ bias) {
    __shared__ float s_sum[8][132];
    __shared__ float s_sq[8][132];
    int tid = threadIdx.x;
    int wp = tid >> 5;
    int lane = tid & 31;
    int gw = blockIdx.x * 8 + wp;

    float4 outv = make_float4(0.f, 0.f, 0.f, 0.f);
    if (gw < Nn) {
        int s = g_base[gw], e = g_base[gw + 1];
        float di = g_dinv[gw];
        float4 accA = make_float4(0.f, 0.f, 0.f, 0.f);
        float4 accB = make_float4(0.f, 0.f, 0.f, 0.f);
        int t = s;
        for (; t + 8 <= e; t += 8) {
            int s0 = g_esrc[t + 0], s1 = g_esrc[t + 1];
            int s2 = g_esrc[t + 2], s3 = g_esrc[t + 3];
            int s4 = g_esrc[t + 4], s5 = g_esrc[t + 5];
            int s6 = g_esrc[t + 6], s7 = g_esrc[t + 7];
            uint2 r0 = *(const uint2*)(g_hwh + (size_t)s0 * 64 + lane * 2);
            uint2 r1 = *(const uint2*)(g_hwh + (size_t)s1 * 64 + lane * 2);
            uint2 r2 = *(const uint2*)(g_hwh + (size_t)s2 * 64 + lane * 2);
            uint2 r3 = *(const uint2*)(g_hwh + (size_t)s3 * 64 + lane * 2);
            uint2 r4 = *(const uint2*)(g_hwh + (size_t)s4 * 64 + lane * 2);
            uint2 r5 = *(const uint2*)(g_hwh + (size_t)s5 * 64 + lane * 2);
            uint2 r6 = *(const uint2*)(g_hwh + (size_t)s6 * 64 + lane * 2);
            uint2 r7 = *(const uint2*)(g_hwh + (size_t)s7 * 64 + lane * 2);
            float2 a0 = __half22float2(*(__half2*)&r0.x), b0 = __half22float2(*(__half2*)&r0.y);
            float2 a1 = __half22float2(*(__half2*)&r1.x), b1 = __half22float2(*(__half2*)&r1.y);
            float2 a2 = __half22float2(*(__half2*)&r2.x), b2 = __half22float2(*(__half2*)&r2.y);
            float2 a3 = __half22float2(*(__half2*)&r3.x), b3 = __half22float2(*(__half2*)&r3.y);
            float2 a4 = __half22float2(*(__half2*)&r4.x), b4 = __half22float2(*(__half2*)&r4.y);
            float2 a5 = __half22float2(*(__half2*)&r5.x), b5 = __half22float2(*(__half2*)&r5.y);
            float2 a6 = __half22float2(*(__half2*)&r6.x), b6 = __half22float2(*(__half2*)&r6.y);
            float2 a7 = __half22float2(*(__half2*)&r7.x), b7 = __half22float2(*(__half2*)&r7.y);
            accA.x += (a0.x + a1.x) + (a2.x + a3.x);
            accA.y += (a0.y + a1.y) + (a2.y + a3.y);
            accA.z += (b0.x + b1.x) + (b2.x + b3.x);
            accA.w += (b0.y + b1.y) + (b2.y + b3.y);
            accB.x += (a4.x + a5.x) + (a6.x + a7.x);
            accB.y += (a4.y + a5.y) + (a6.y + a7.y);
            accB.z += (b4.x + b5.x) + (b6.x + b7.x);
            accB.w += (b4.y + b5.y) + (b6.y + b7.y);
        }
        for (; t < e; t++) {
            int s0 = g_esrc[t];
            uint2 r0 = *(const uint2*)(g_hwh + (size_t)s0 * 64 + lane * 2);
            float2 a0 = __half22float2(*(__half2*)&r0.x), b0 = __half22float2(*(__half2*)&r0.y);
            accA.x += a0.x; accA.y += a0.y;
            accA.z += b0.x; accA.w += b0.y;
        }
        // self row (already scaled by dinv[gw])
        uint2 rs = *(const uint2*)(g_hwh + (size_t)gw * 64 + lane * 2);
        float2 ha = __half22float2(*(__half2*)&rs.x), hb = __half22float2(*(__half2*)&rs.y);
        accA.x += ha.x + accB.x; accA.y += ha.y + accB.y;
        accA.z += hb.x + accB.z; accA.w += hb.y + accB.w;
        float4 bv = *(const float4*)(bias + lane * 4);
        outv.x = accA.x * di + bv.x;
        outv.y = accA.y * di + bv.y;
        outv.z = accA.z * di + bv.z;
        outv.w = accA.w * di + bv.w;
        *(float4*)(g_agg + (size_t)gw * Hh + lane * 4) = outv;
    }
    s_sum[wp][lane * 4 + 0] = outv.x; s_sq[wp][lane * 4 + 0] = outv.x * outv.x;
    s_sum[wp][lane * 4 + 1] = outv.y; s_sq[wp][lane * 4 + 1] = outv.y * outv.y;
    s_sum[wp][lane * 4 + 2] = outv.z; s_sq[wp][lane * 4 + 2] = outv.z * outv.z;
    s_sum[wp][lane * 4 + 3] = outv.w; s_sq[wp][lane * 4 + 3] = outv.w * outv.w;
    __syncthreads();
    if (tid < 128) {
        float s = 0.f, q = 0.f;
#pragma unroll
        for (int w = 0; w < 8; w++) { s += s_sum[w][tid]; q += s_sq[w][tid]; }
        atomicAdd(&g_bnsum[layer * Hh + tid], s);
        atomicAdd(&g_bnsq[layer * Hh + tid], q);
    }
}

// ---------------- tensor-core GEMM: relu(bn(A)) @ W -> hw (pre-scaled fp16) ----------------
#define GEMM_SMEM (2 * 128 * Pp * 2)
__global__ void __launch_bounds__(256)
k_gemm(int layer, const float* __restrict__ gamma, const float* __restrict__ beta,
       const float* __restrict__ W) {
    extern __shared__ __half smh[];
    __half* As = smh;                 // 128 x Pp
    __half* Wt = smh + 128 * Pp;      // 128 x Pp (transposed W: Wt[n][k])
    __shared__ float s_scale[128];
    __shared__ float s_shift[128];
    int tid = threadIdx.x;
    int row0 = blockIdx.x * 128;

    if (tid < 128) {
        float mean = g_bnsum[layer * Hh + tid] * (1.0f / Nn);
        float var = g_bnsq[layer * Hh + tid] * (1.0f / Nn) - mean * mean;
        float sc = gamma[tid] * rsqrtf(var + EPSf);
        s_scale[tid] = sc;
        s_shift[tid] = beta[tid] - mean * sc;
    }

    // load W transposed into Wt as fp16
    for (int t = tid; t < 128 * 32; t += 256) {
        int k = t >> 5, n0 = (t & 31) * 4;
        float4 wv = ((const float4*)W)[t];
        Wt[(n0 + 0) * Pp + k] = __float2half_rn(wv.x);
        Wt[(n0 + 1) * Pp + k] = __float2half_rn(wv.y);
        Wt[(n0 + 2) * Pp + k] = __float2half_rn(wv.z);
        Wt[(n0 + 3) * Pp + k] = __float2half_rn(wv.w);
    }
    __syncthreads();

    // load A tile with BN+ReLU, convert to fp16, zero-pad OOB rows
    for (int t = tid; t < 128 * 32; t += 256) {
        int r = t >> 5, q = t & 31;
        int grow = row0 + r;
        float4 v = make_float4(0.f, 0.f, 0.f, 0.f);
        if (grow < Nn) {
            v = ((const float4*)(g_agg + (size_t)grow * Hh))[q];
            float4 sc = ((const float4*)s_scale)[q];
            float4 sh = ((const float4*)s_shift)[q];
            v.x = fmaxf(v.x * sc.x + sh.x, 0.f);
            v.y = fmaxf(v.y * sc.y + sh.y, 0.f);
            v.z = fmaxf(v.z * sc.z + sh.z, 0.f);
            v.w = fmaxf(v.w * sc.w + sh.w, 0.f);
        }
        __half2 h0 = __floats2half2_rn(v.x, v.y);
        __half2 h1 = __floats2half2_rn(v.z, v.w);
        uint2 u = make_uint2(*(unsigned*)&h0, *(unsigned*)&h1);
        *(uint2*)(As + r * Pp + q * 4) = u;
    }
    __syncthreads();

    int wp = tid >> 5;        // warp 0..7 -> rows wp*16 .. +15
    int lane = tid & 31;
    int g = lane >> 2;        // groupID 0..7
    int tg = lane & 3;        // threadID_in_group 0..3

    float4 c[16];
#pragma unroll
    for (int nt = 0; nt < 16; nt++) c[nt] = make_float4(0.f, 0.f, 0.f, 0.f);

    const __half* Abase = As + (wp * 16 + g) * Pp + 2 * tg;
#pragma unroll
    for (int kk = 0; kk < 8; kk++) {
        const __half* Ar = Abase + kk * 16;
        unsigned a0 = *(const unsigned*)(Ar);
        unsigned a1 = *(const unsigned*)(Ar + 8 * Pp);
        unsigned a2 = *(const unsigned*)(Ar + 8);
        unsigned a3 = *(const unsigned*)(Ar + 8 * Pp + 8);
        const __half* Bb = Wt + g * Pp + kk * 16 + 2 * tg;
#pragma unroll
        for (int nt = 0; nt < 16; nt++) {
            const __half* Br = Bb + nt * 8 * Pp;
            unsigned b0 = *(const unsigned*)(Br);
            unsigned b1 = *(const unsigned*)(Br + 8);
            mma16816(c[nt], a0, a1, a2, a3, b0, b1);
        }
    }

    // epilogue: pre-scale by dinv[row], fp16 half2 stores
    int r_lo = row0 + wp * 16 + g;
    int r_hi = r_lo + 8;
    bool ok_lo = (r_lo < Nn), ok_hi = (r_hi < Nn);
    float d_lo = ok_lo ? g_dinv[r_lo] : 0.f;
    float d_hi = ok_hi ? g_dinv[r_hi] : 0.f;
    __half2* out_lo = g_hwh + (size_t)r_lo * 64 + tg;
    __half2* out_hi = g_hwh + (size_t)r_hi * 64 + tg;
#pragma unroll
    for (int nt = 0; nt < 16; nt++) {
        if (ok_lo) out_lo[nt * 4] = __floats2half2_rn(c[nt].x * d_lo, c[nt].y * d_lo);
        if (ok_hi) out_hi[nt * 4] = __floats2half2_rn(c[nt].z * d_hi, c[nt].w * d_hi);
    }
}

// ---------------- pooling: batch is sorted -> run-length accumulate ----------------
__global__ void k_pool(const int* __restrict__ batch,
                       const float* __restrict__ gamma, const float* __restrict__ beta) {
    __shared__ int sb[128];
    int c = threadIdx.x;
    int r0 = blockIdx.x * 128;
    int nrows = min(128, Nn - r0);
    if (c < nrows) sb[c] = batch[r0 + c];
    float mean = g_bnsum[2 * Hh + c] * (1.0f / Nn);
    float var = g_bnsq[2 * Hh + c] * (1.0f / Nn) - mean * mean;
    float sc = gamma[c] * rsqrtf(var + EPSf);
    float sh = beta[c] - mean * sc;
    __syncthreads();
    float acc = 0.f;
    int cur = sb[0];
    for (int r = 0; r < nrows; r++) {
        int gr = sb[r];
        if (gr != cur) { atomicAdd(&g_pooled[cur * Hh + c], acc); acc = 0.f; cur = gr; }
        float v = g_agg[(size_t)(r0 + r) * Hh + c];
        acc += fmaxf(v * sc + sh, 0.f);
    }
    atomicAdd(&g_pooled[cur * Hh + c], acc);
}

// ---------------- final FC + TAIL ZEROING for next replay ----------------
__global__ void k_fc(const float* __restrict__ fcW, const float* __restrict__ fcb,
                     float* __restrict__ out) {
    int g = blockIdx.x, c = threadIdx.x;
    int t = g * 128 + c;                        // 0..65535 global thread id
    float v = g_pooled[g * Hh + c] / fmaxf(g_cnt[g], 1.0f);
    g_pooled[g * Hh + c] = 0.0f;                // zero own slot after read
    __shared__ float s0[128], s1[128], s2[128];
    s0[c] = v * fcW[c * 3 + 0];
    s1[c] = v * fcW[c * 3 + 1];
    s2[c] = v * fcW[c * 3 + 2];
    __syncthreads();
    for (int off = 64; off > 0; off >>= 1) {
        if (c < off) { s0[c] += s0[c + off]; s1[c] += s1[c + off]; s2[c] += s2[c + off]; }
        __syncthreads();
    }
    if (c == 0) {
        out[g * 3 + 0] = s0[0] + fcb[0];
        out[g * 3 + 1] = s1[0] + fcb[1];
        out[g * 3 + 2] = s2[0] + fcb[2];
        g_cnt[g] = 0.0f;                        // all reads of cnt[g] done (pre-sync)
    }
    // tail zeroing of per-replay scratch (65536 threads cover everything)
    if (t < Nn) { g_degcnt[t] = 0; g_cursor[t] = 0; }
    if (t < SCAN_BLKS) g_sflag[t] = 0;
    if (t < 3 * Hh) { g_bnsum[t] = 0.0f; g_bnsq[t] = 0.0f; }
}

// ---------------- launch ----------------
extern "C" void kernel_launch(void* const* d_in, const int* in_sizes, int n_in,
                              void* d_out, int out_size) {
    const float* x     = (const float*)d_in[0];
    const int*   ei    = (const int*)  d_in[1];
    const int*   batch = (const int*)  d_in[2];
    const float* emb0  = (const float*)d_in[3];
    const float* emb1  = (const float*)d_in[4];
    const float* emb2  = (const float*)d_in[5];
    const float* emb5  = (const float*)d_in[6];
    const float* W1    = (const float*)d_in[7];
    const float* b1    = (const float*)d_in[8];
    const float* W2    = (const float*)d_in[9];
    const float* b2    = (const float*)d_in[10];
    const float* W3    = (const float*)d_in[11];
    const float* b3    = (const float*)d_in[12];
    const float* g1    = (const float*)d_in[13];
    const float* be1   = (const float*)d_in[14];
    const float* g2    = (const float*)d_in[15];
    const float* be2   = (const float*)d_in[16];
    const float* g3    = (const float*)d_in[17];
    const float* be3   = (const float*)d_in[18];
    const float* fcW   = (const float*)d_in[19];
    const float* fcb   = (const float*)d_in[20];
    float* out = (float*)d_out;

    cudaFuncSetAttribute(k_gemm, cudaFuncAttributeMaxDynamicSharedMemorySize, GEMM_SMEM);

    const int nblk = (Nn + 127) / 128;          // 391
    const int gblk = (Nn + 7) / 8;              // gather blocks (8 warps = 8 nodes)

    // 10-kernel critical path
    k_count<<<E4BLK, 256>>>(ei, batch);
    k_scan_proj<<<SCAN_BLKS + PROJ_BLKS, 256>>>(emb0, emb1, emb2, emb5, W1);
    k_place_layer1<<<E4BLK + L1BLK, 256>>>(ei, x, W1);

    k_gather<<<gblk, 256>>>(0, b1);
    k_gemm<<<nblk, 256, GEMM_SMEM>>>(0, g1, be1, W2);
    k_gather<<<gblk, 256>>>(1, b2);
    k_gemm<<<nblk, 256, GEMM_SMEM>>>(1, g2, be2, W3);
    k_gather<<<gblk, 256>>>(2, b3);

    k_pool<<<nblk, 128>>>(batch, g3, be3);
    k_fc<<<Gg, 128>>>(fcW, fcb, out);
}

// round 10
// speedup vs baseline: 1.4912x; 1.0042x over previous
#include <cuda_runtime.h>
#include <cuda_fp16.h>
#include <cstdint>

#define Nn 50000
#define Ee 600000
#define Gg 512
#define Hh 128
#define SCAN_BLKS ((Nn + 255) / 256)   // 196
#define PROJ_BLKS 235                   // ceil(470/2), 2 table rows per 256-thr block
#define E4BLK ((Ee / 4 + 255) / 256)    // 586
#define L1BLK ((Nn + 3) / 4)            // 12500
#define EPSf 1e-5f
#define Pp 136                          // smem pitch in halfs (conflict-free)

typedef unsigned long long u64;

// ---------------- device scratch (no allocations allowed) ----------------
// g_hwh holds (h @ W) * dinv[row] in fp16 (row = 256B). Row Nn is a reserved
// ALL-ZERO row (never written) used to pad gather chunks branch-free.
__device__ __align__(16) __half2 g_hwh[(size_t)(Nn + 1) * 64];
__device__ __align__(16) float g_agg[(size_t)Nn * Hh];     // aggregated (GEMM/pool input)
__device__ __align__(16) float g_P[470 * Hh];              // projected embedding tables
__device__ __align__(16) float g_dinv[Nn];
__device__ __align__(16) float g_bnsum[3 * Hh];
__device__ __align__(16) float g_bnsq[3 * Hh];
__device__ __align__(16) float g_pooled[Gg * Hh];
__device__ __align__(16) float g_cnt[Gg];
__device__ int g_degcnt[Nn];
__device__ int g_cursor[Nn];
__device__ int g_base[Nn + 1];
__device__ int g_esrc[Ee];
__device__ int g_sflag[SCAN_BLKS];     // lookback flags: (aggregate<<1)|1

// NOTE: all per-replay zeroing of g_degcnt/g_cursor/g_bnsum/g_bnsq/g_sflag/
// g_pooled/g_cnt happens at the TAIL of the graph (k_fc). First execution
// relies on CUDA zero-initialization of __device__ globals.

// ---------------- warp scan helper ----------------
__device__ __forceinline__ int warp_incl_scan(int v, int lane) {
#pragma unroll
    for (int off = 1; off < 32; off <<= 1) {
        int y = __shfl_up_sync(0xFFFFFFFFu, v, off);
        if (lane >= off) v += y;
    }
    return v;
}

// ---------------- HMMA m16n8k16 fp16 -> fp32 ----------------
__device__ __forceinline__ void mma16816(float4& c, unsigned a0, unsigned a1,
                                         unsigned a2, unsigned a3,
                                         unsigned b0, unsigned b1) {
    asm volatile(
        "mma.sync.aligned.m16n8k16.row.col.f32.f16.f16.f32 "
        "{%0,%1,%2,%3}, {%4,%5,%6,%7}, {%8,%9}, {%0,%1,%2,%3};"
        : "+f"(c.x), "+f"(c.y), "+f"(c.z), "+f"(c.w)
        : "r"(a0), "r"(a1), "r"(a2), "r"(a3), "r"(b0), "r"(b1));
}

// ---------------- degree count + graph-size count (int4 vectorized) ----------------
__global__ void k_count(const int* __restrict__ ei, const int* __restrict__ batch) {
    int j = blockIdx.x * blockDim.x + threadIdx.x;
    if (j < Ee / 4) {
        int4 d = ((const int4*)(ei + Ee))[j];
        atomicAdd(&g_degcnt[d.x], 1);
        atomicAdd(&g_degcnt[d.y], 1);
        atomicAdd(&g_degcnt[d.z], 1);
        atomicAdd(&g_degcnt[d.w], 1);
    }
    if (j < Nn / 4) {
        int4 b = ((const int4*)batch)[j];
        atomicAdd(&g_cnt[b.x], 1.0f);
        atomicAdd(&g_cnt[b.y], 1.0f);
        atomicAdd(&g_cnt[b.z], 1.0f);
        atomicAdd(&g_cnt[b.w], 1.0f);
    }
}

// ---------------- fused: decoupled-lookback scan (blocks 0..195) + W1-projection
__global__ void __launch_bounds__(256) k_scan_proj(
    const float* __restrict__ emb0, const float* __restrict__ emb1,
    const float* __restrict__ emb2, const float* __restrict__ emb5,
    const float* __restrict__ W1) {
    int bid = blockIdx.x;
    int tid = threadIdx.x;

    if (bid >= SCAN_BLKS) {
        // ---- projection part: 2 table rows per block ----
        int idx = (bid - SCAN_BLKS) * 2 + (tid >> 7);
        if (idx >= 470) return;
        int c = tid & 127;
        const float* emb; int koff, v;
        if (idx < 96)       { emb = emb0; koff = 1;  v = idx; }
        else if (idx < 192) { emb = emb1; koff = 33; v = idx - 96; }
        else if (idx < 288) { emb = emb2; koff = 65; v = idx - 192; }
        else                { emb = emb5; koff = 97; v = idx - 288; }
        float acc = 0.0f;
#pragma unroll
        for (int j = 0; j < 32; j++)
            acc += emb[v * 32 + j] * W1[(koff + j) * Hh + c];
        g_P[(size_t)idx * Hh + c] = acc;
        return;
    }

    // ---- scan part ----
    __shared__ int wsum[8];
    __shared__ int wred[8];
    int lane = tid & 31, wp = tid >> 5;
    int i = bid * 256 + tid;
    int v = (i < Nn) ? g_degcnt[i] : 0;
    int incl = warp_incl_scan(v, lane);
    if (lane == 31) wsum[wp] = incl;
    __syncthreads();
    int woff = 0, total = 0;
#pragma unroll
    for (int w = 0; w < 8; w++) {
        woff += (w < wp) ? wsum[w] : 0;
        total += wsum[w];
    }
    int excl = woff + incl - v;

    if (tid == 0) atomicExch(&g_sflag[bid], (total << 1) | 1);

    int mysum = 0;
    if (tid < bid) {
        int f;
        do { f = atomicAdd(&g_sflag[tid], 0); } while (!(f & 1));
        mysum = f >> 1;
    }
#pragma unroll
    for (int off = 16; off > 0; off >>= 1)
        mysum += __shfl_down_sync(0xFFFFFFFFu, mysum, off);
    if (lane == 0) wred[wp] = mysum;
    __syncthreads();
    int prefix = 0;
#pragma unroll
    for (int w = 0; w < 8; w++) prefix += wred[w];

    if (i < Nn) {
        g_base[i] = excl + prefix;
        g_dinv[i] = rsqrtf((float)g_degcnt[i] + 1.0f);
    }
    if (i == 0) g_base[Nn] = Ee;
}

// ---------------- fused: CSR edge placement + layer-1 hw production ----------------
__global__ void __launch_bounds__(256) k_place_layer1(
    const int* __restrict__ ei, const float* __restrict__ x,
    const float* __restrict__ W1) {
    int tid = threadIdx.x;
    if (blockIdx.x < E4BLK) {
        int j = blockIdx.x * 256 + tid;
        if (j >= Ee / 4) return;
        int4 s = ((const int4*)ei)[j];
        int4 d = ((const int4*)(ei + Ee))[j];
        g_esrc[g_base[d.x] + atomicAdd(&g_cursor[d.x], 1)] = s.x;
        g_esrc[g_base[d.y] + atomicAdd(&g_cursor[d.y], 1)] = s.y;
        g_esrc[g_base[d.z] + atomicAdd(&g_cursor[d.z], 1)] = s.z;
        g_esrc[g_base[d.w] + atomicAdd(&g_cursor[d.w], 1)] = s.w;
        return;
    }
    int node = (blockIdx.x - E4BLK) * 4 + (tid >> 6);
    if (node >= Nn) return;
    int c2 = tid & 63;
    int c0 = c2 * 2;
    const float* xr = x + (size_t)node * 5;
    float pos = xr[0];
    int i0 = (int)xr[1], i1 = (int)xr[2], i2 = (int)xr[3], i5 = (int)xr[4];
    const float* p0 = g_P + (size_t)i0 * Hh;
    const float* p1 = g_P + (size_t)(96 + i1) * Hh;
    const float* p2 = g_P + (size_t)(192 + i2) * Hh;
    const float* p5 = g_P + (size_t)(288 + i5) * Hh;
    float di = g_dinv[node];
    float va = (pos * W1[c0]     + p0[c0]     + p1[c0]     + p2[c0]     + p5[c0]) * di;
    float vb = (pos * W1[c0 + 1] + p0[c0 + 1] + p1[c0 + 1] + p2[c0 + 1] + p5[c0 + 1]) * di;
    g_hwh[(size_t)node * 64 + c2] = __floats2half2_rn(va, vb);
}

// ---------------- fused aggregation + self-loop + bias + BN partial stats ------
// Latency-optimized: lane-parallel index fetch (one coalesced LDG per 32 edges),
// shuffle-broadcast indices, zero-row (index Nn) padding -> branch-free inner
// loop of 8 independent row loads; no scalar remainder loop.
__global__ void __launch_bounds__(256) k_gather(int layer, const float* __restrict__ bias) {
    __shared__ float s_sum[8][132];
    __shared__ float s_sq[8][132];
    int tid = threadIdx.x;
    int wp = tid >> 5;
    int lane = tid & 31;
    int gw = blockIdx.x * 8 + wp;

    float4 outv = make_float4(0.f, 0.f, 0.f, 0.f);
    if (gw < Nn) {
        int s = g_base[gw], e = g_base[gw + 1];
        int deg = e - s;
        float di = g_dinv[gw];
        float4 accA = make_float4(0.f, 0.f, 0.f, 0.f);
        float4 accB = make_float4(0.f, 0.f, 0.f, 0.f);
        const __half2* hw = g_hwh;

        for (int base = 0; base < deg; base += 32) {
            int cnt = deg - base; if (cnt > 32) cnt = 32;
            // one coalesced index load for up to 32 edges; pad with zero-row Nn
            int idx = (lane < cnt) ? g_esrc[s + base + lane] : Nn;
            int cntR = (cnt + 7) & ~7;           // <= 32
            for (int j = 0; j < cntR; j += 8) {
                int i0 = __shfl_sync(0xFFFFFFFFu, idx, j + 0);
                int i1 = __shfl_sync(0xFFFFFFFFu, idx, j + 1);
                int i2 = __shfl_sync(0xFFFFFFFFu, idx, j + 2);
                int i3 = __shfl_sync(0xFFFFFFFFu, idx, j + 3);
                int i4 = __shfl_sync(0xFFFFFFFFu, idx, j + 4);
                int i5 = __shfl_sync(0xFFFFFFFFu, idx, j + 5);
                int i6 = __shfl_sync(0xFFFFFFFFu, idx, j + 6);
                int i7 = __shfl_sync(0xFFFFFFFFu, idx, j + 7);
                uint2 r0 = *(const uint2*)(hw + (size_t)i0 * 64 + lane * 2);
                uint2 r1 = *(const uint2*)(hw + (size_t)i1 * 64 + lane * 2);
                uint2 r2 = *(const uint2*)(hw + (size_t)i2 * 64 + lane * 2);
                uint2 r3 = *(const uint2*)(hw + (size_t)i3 * 64 + lane * 2);
                uint2 r4 = *(const uint2*)(hw + (size_t)i4 * 64 + lane * 2);
                uint2 r5 = *(const uint2*)(hw + (size_t)i5 * 64 + lane * 2);
                uint2 r6 = *(const uint2*)(hw + (size_t)i6 * 64 + lane * 2);
                uint2 r7 = *(const uint2*)(hw + (size_t)i7 * 64 + lane * 2);
                float2 a0 = __half22float2(*(__half2*)&r0.x), b0 = __half22float2(*(__half2*)&r0.y);
                float2 a1 = __half22float2(*(__half2*)&r1.x), b1 = __half22float2(*(__half2*)&r1.y);
                float2 a2 = __half22float2(*(__half2*)&r2.x), b2 = __half22float2(*(__half2*)&r2.y);
                float2 a3 = __half22float2(*(__half2*)&r3.x), b3 = __half22float2(*(__half2*)&r3.y);
                float2 a4 = __half22float2(*(__half2*)&r4.x), b4 = __half22float2(*(__half2*)&r4.y);
                float2 a5 = __half22float2(*(__half2*)&r5.x), b5 = __half22float2(*(__half2*)&r5.y);
                float2 a6 = __half22float2(*(__half2*)&r6.x), b6 = __half22float2(*(__half2*)&r6.y);
                float2 a7 = __half22float2(*(__half2*)&r7.x), b7 = __half22float2(*(__half2*)&r7.y);
                accA.x += (a0.x + a1.x) + (a2.x + a3.x);
                accA.y += (a0.y + a1.y) + (a2.y + a3.y);
                accA.z += (b0.x + b1.x) + (b2.x + b3.x);
                accA.w += (b0.y + b1.y) + (b2.y + b3.y);
                accB.x += (a4.x + a5.x) + (a6.x + a7.x);
                accB.y += (a4.y + a5.y) + (a6.y + a7.y);
                accB.z += (b4.x + b5.x) + (b6.x + b7.x);
                accB.w += (b4.y + b5.y) + (b6.y + b7.y);
            }
        }
        // self row (already scaled by dinv[gw])
        uint2 rs = *(const uint2*)(g_hwh + (size_t)gw * 64 + lane * 2);
        float2 ha = __half22float2(*(__half2*)&rs.x), hb = __half22float2(*(__half2*)&rs.y);
        accA.x += ha.x + accB.x; accA.y += ha.y + accB.y;
        accA.z += hb.x + accB.z; accA.w += hb.y + accB.w;
        float4 bv = *(const float4*)(bias + lane * 4);
        outv.x = accA.x * di + bv.x;
        outv.y = accA.y * di + bv.y;
        outv.z = accA.z * di + bv.z;
        outv.w = accA.w * di + bv.w;
        *(float4*)(g_agg + (size_t)gw * Hh + lane * 4) = outv;
    }
    s_sum[wp][lane * 4 + 0] = outv.x; s_sq[wp][lane * 4 + 0] = outv.x * outv.x;
    s_sum[wp][lane * 4 + 1] = outv.y; s_sq[wp][lane * 4 + 1] = outv.y * outv.y;
    s_sum[wp][lane * 4 + 2] = outv.z; s_sq[wp][lane * 4 + 2] = outv.z * outv.z;
    s_sum[wp][lane * 4 + 3] = outv.w; s_sq[wp][lane * 4 + 3] = outv.w * outv.w;
    __syncthreads();
    if (tid < 128) {
        float s = 0.f, q = 0.f;
#pragma unroll
        for (int w = 0; w < 8; w++) { s += s_sum[w][tid]; q += s_sq[w][tid]; }
        atomicAdd(&g_bnsum[layer * Hh + tid], s);
        atomicAdd(&g_bnsq[layer * Hh + tid], q);
    }
}

// ---------------- tensor-core GEMM: relu(bn(A)) @ W -> hw (pre-scaled fp16) ----------------
#define GEMM_SMEM (2 * 128 * Pp * 2)
__global__ void __launch_bounds__(256)
k_gemm(int layer, const float* __restrict__ gamma, const float* __restrict__ beta,
       const float* __restrict__ W) {
    extern __shared__ __half smh[];
    __half* As = smh;                 // 128 x Pp
    __half* Wt = smh + 128 * Pp;      // 128 x Pp (transposed W: Wt[n][k])
    __shared__ float s_scale[128];
    __shared__ float s_shift[128];
    int tid = threadIdx.x;
    int row0 = blockIdx.x * 128;

    if (tid < 128) {
        float mean = g_bnsum[layer * Hh + tid] * (1.0f / Nn);
        float var = g_bnsq[layer * Hh + tid] * (1.0f / Nn) - mean * mean;
        float sc = gamma[tid] * rsqrtf(var + EPSf);
        s_scale[tid] = sc;
        s_shift[tid] = beta[tid] - mean * sc;
    }

    for (int t = tid; t < 128 * 32; t += 256) {
        int k = t >> 5, n0 = (t & 31) * 4;
        float4 wv = ((const float4*)W)[t];
        Wt[(n0 + 0) * Pp + k] = __float2half_rn(wv.x);
        Wt[(n0 + 1) * Pp + k] = __float2half_rn(wv.y);
        Wt[(n0 + 2) * Pp + k] = __float2half_rn(wv.z);
        Wt[(n0 + 3) * Pp + k] = __float2half_rn(wv.w);
    }
    __syncthreads();

    for (int t = tid; t < 128 * 32; t += 256) {
        int r = t >> 5, q = t & 31;
        int grow = row0 + r;
        float4 v = make_float4(0.f, 0.f, 0.f, 0.f);
        if (grow < Nn) {
            v = ((const float4*)(g_agg + (size_t)grow * Hh))[q];
            float4 sc = ((const float4*)s_scale)[q];
            float4 sh = ((const float4*)s_shift)[q];
            v.x = fmaxf(v.x * sc.x + sh.x, 0.f);
            v.y = fmaxf(v.y * sc.y + sh.y, 0.f);
            v.z = fmaxf(v.z * sc.z + sh.z, 0.f);
            v.w = fmaxf(v.w * sc.w + sh.w, 0.f);
        }
        __half2 h0 = __floats2half2_rn(v.x, v.y);
        __half2 h1 = __floats2half2_rn(v.z, v.w);
        uint2 u = make_uint2(*(unsigned*)&h0, *(unsigned*)&h1);
        *(uint2*)(As + r * Pp + q * 4) = u;
    }
    __syncthreads();

    int wp = tid >> 5;
    int lane = tid & 31;
    int g = lane >> 2;
    int tg = lane & 3;

    float4 c[16];
#pragma unroll
    for (int nt = 0; nt < 16; nt++) c[nt] = make_float4(0.f, 0.f, 0.f, 0.f);

    const __half* Abase = As + (wp * 16 + g) * Pp + 2 * tg;
#pragma unroll
    for (int kk = 0; kk < 8; kk++) {
        const __half* Ar = Abase + kk * 16;
        unsigned a0 = *(const unsigned*)(Ar);
        unsigned a1 = *(const unsigned*)(Ar + 8 * Pp);
        unsigned a2 = *(const unsigned*)(Ar + 8);
        unsigned a3 = *(const unsigned*)(Ar + 8 * Pp + 8);
        const __half* Bb = Wt + g * Pp + kk * 16 + 2 * tg;
#pragma unroll
        for (int nt = 0; nt < 16; nt++) {
            const __half* Br = Bb + nt * 8 * Pp;
            unsigned b0 = *(const unsigned*)(Br);
            unsigned b1 = *(const unsigned*)(Br + 8);
            mma16816(c[nt], a0, a1, a2, a3, b0, b1);
        }
    }

    int r_lo = row0 + wp * 16 + g;
    int r_hi = r_lo + 8;
    bool ok_lo = (r_lo < Nn), ok_hi = (r_hi < Nn);
    float d_lo = ok_lo ? g_dinv[r_lo] : 0.f;
    float d_hi = ok_hi ? g_dinv[r_hi] : 0.f;
    __half2* out_lo = g_hwh + (size_t)r_lo * 64 + tg;
    __half2* out_hi = g_hwh + (size_t)r_hi * 64 + tg;
#pragma unroll
    for (int nt = 0; nt < 16; nt++) {
        if (ok_lo) out_lo[nt * 4] = __floats2half2_rn(c[nt].x * d_lo, c[nt].y * d_lo);
        if (ok_hi) out_hi[nt * 4] = __floats2half2_rn(c[nt].z * d_hi, c[nt].w * d_hi);
    }
}

// ---------------- pooling: batch is sorted -> run-length accumulate ----------------
__global__ void k_pool(const int* __restrict__ batch,
                       const float* __restrict__ gamma, const float* __restrict__ beta) {
    __shared__ int sb[128];
    int c = threadIdx.x;
    int r0 = blockIdx.x * 128;
    int nrows = min(128, Nn - r0);
    if (c < nrows) sb[c] = batch[r0 + c];
    float mean = g_bnsum[2 * Hh + c] * (1.0f / Nn);
    float var = g_bnsq[2 * Hh + c] * (1.0f / Nn) - mean * mean;
    float sc = gamma[c] * rsqrtf(var + EPSf);
    float sh = beta[c] - mean * sc;
    __syncthreads();
    float acc = 0.f;
    int cur = sb[0];
    for (int r = 0; r < nrows; r++) {
        int gr = sb[r];
        if (gr != cur) { atomicAdd(&g_pooled[cur * Hh + c], acc); acc = 0.f; cur = gr; }
        float v = g_agg[(size_t)(r0 + r) * Hh + c];
        acc += fmaxf(v * sc + sh, 0.f);
    }
    atomicAdd(&g_pooled[cur * Hh + c], acc);
}

// ---------------- final FC + TAIL ZEROING for next replay ----------------
__global__ void k_fc(const float* __restrict__ fcW, const float* __restrict__ fcb,
                     float* __restrict__ out) {
    int g = blockIdx.x, c = threadIdx.x;
    int t = g * 128 + c;
    float v = g_pooled[g * Hh + c] / fmaxf(g_cnt[g], 1.0f);
    g_pooled[g * Hh + c] = 0.0f;
    __shared__ float s0[128], s1[128], s2[128];
    s0[c] = v * fcW[c * 3 + 0];
    s1[c] = v * fcW[c * 3 + 1];
    s2[c] = v * fcW[c * 3 + 2];
    __syncthreads();
    for (int off = 64; off > 0; off >>= 1) {
        if (c < off) { s0[c] += s0[c + off]; s1[c] += s1[c + off]; s2[c] += s2[c + off]; }
        __syncthreads();
    }
    if (c == 0) {
        out[g * 3 + 0] = s0[0] + fcb[0];
        out[g * 3 + 1] = s1[0] + fcb[1];
        out[g * 3 + 2] = s2[0] + fcb[2];
        g_cnt[g] = 0.0f;
    }
    if (t < Nn) { g_degcnt[t] = 0; g_cursor[t] = 0; }
    if (t < SCAN_BLKS) g_sflag[t] = 0;
    if (t < 3 * Hh) { g_bnsum[t] = 0.0f; g_bnsq[t] = 0.0f; }
}

// ---------------- launch ----------------
extern "C" void kernel_launch(void* const* d_in, const int* in_sizes, int n_in,
                              void* d_out, int out_size) {
    const float* x     = (const float*)d_in[0];
    const int*   ei    = (const int*)  d_in[1];
    const int*   batch = (const int*)  d_in[2];
    const float* emb0  = (const float*)d_in[3];
    const float* emb1  = (const float*)d_in[4];
    const float* emb2  = (const float*)d_in[5];
    const float* emb5  = (const float*)d_in[6];
    const float* W1    = (const float*)d_in[7];
    const float* b1    = (const float*)d_in[8];
    const float* W2    = (const float*)d_in[9];
    const float* b2    = (const float*)d_in[10];
    const float* W3    = (const float*)d_in[11];
    const float* b3    = (const float*)d_in[12];
    const float* g1    = (const float*)d_in[13];
    const float* be1   = (const float*)d_in[14];
    const float* g2    = (const float*)d_in[15];
    const float* be2   = (const float*)d_in[16];
    const float* g3    = (const float*)d_in[17];
    const float* be3   = (const float*)d_in[18];
    const float* fcW   = (const float*)d_in[19];
    const float* fcb   = (const float*)d_in[20];
    float* out = (float*)d_out;

    cudaFuncSetAttribute(k_gemm, cudaFuncAttributeMaxDynamicSharedMemorySize, GEMM_SMEM);

    const int nblk = (Nn + 127) / 128;          // 391
    const int gblk = (Nn + 7) / 8;              // gather blocks (8 warps = 8 nodes)

    // 10-kernel critical path
    k_count<<<E4BLK, 256>>>(ei, batch);
    k_scan_proj<<<SCAN_BLKS + PROJ_BLKS, 256>>>(emb0, emb1, emb2, emb5, W1);
    k_place_layer1<<<E4BLK + L1BLK, 256>>>(ei, x, W1);

    k_gather<<<gblk, 256>>>(0, b1);
    k_gemm<<<nblk, 256, GEMM_SMEM>>>(0, g1, be1, W2);
    k_gather<<<gblk, 256>>>(1, b2);
    k_gemm<<<nblk, 256, GEMM_SMEM>>>(1, g2, be2, W3);
    k_gather<<<gblk, 256>>>(2, b3);

    k_pool<<<nblk, 128>>>(batch, g3, be3);
    k_fc<<<Gg, 128>>>(fcW, fcb, out);
}

// round 11
// speedup vs baseline: 1.5046x; 1.0090x over previous
#include <cuda_runtime.h>
#include <cuda_fp16.h>
#include <cstdint>

#define Nn 50000
#define Ee 600000
#define Gg 512
#define Hh 128
#define SCAN_BLKS ((Nn + 255) / 256)   // 196
#define PROJ_BLKS 235                   // ceil(470/2), 2 table rows per 256-thr block
#define E4BLK ((Ee / 4 + 255) / 256)    // 586
#define L1BLK ((Nn + 3) / 4)            // 12500
#define EPSf 1e-5f
#define Pp 136                          // smem pitch in halfs (conflict-free)

typedef unsigned long long u64;

// ---------------- device scratch (no allocations allowed) ----------------
// g_hwh holds (h @ W) * dinv[row] in fp16 (row = 256B). Row Nn is a reserved
// ALL-ZERO row (never written) used to pad gather chunks branch-free.
__device__ __align__(16) __half2 g_hwh[(size_t)(Nn + 1) * 64];
__device__ __align__(16) float g_agg[(size_t)Nn * Hh];     // aggregated (GEMM/pool input)
__device__ __align__(16) float g_P[470 * Hh];              // projected embedding tables
__device__ __align__(16) float g_dinv[Nn];
__device__ __align__(16) float g_bnsum[3 * Hh];
__device__ __align__(16) float g_bnsq[3 * Hh];
__device__ __align__(16) float g_pooled[Gg * Hh];
__device__ __align__(16) float g_cnt[Gg];
__device__ int g_degcnt[Nn];
__device__ int g_cursor[Nn];
__device__ int g_base[Nn + 1];
__device__ int g_esrc[Ee];
__device__ int g_sflag[SCAN_BLKS];     // lookback flags: (aggregate<<1)|1

// NOTE: per-replay zeroing of scratch happens at the TAIL of the graph (k_fc).
// First execution relies on CUDA zero-initialization of __device__ globals.

// ---------------- warp scan helper ----------------
__device__ __forceinline__ int warp_incl_scan(int v, int lane) {
#pragma unroll
    for (int off = 1; off < 32; off <<= 1) {
        int y = __shfl_up_sync(0xFFFFFFFFu, v, off);
        if (lane >= off) v += y;
    }
    return v;
}

// ---------------- HMMA m16n8k16 fp16 -> fp32 ----------------
__device__ __forceinline__ void mma16816(float4& c, unsigned a0, unsigned a1,
                                         unsigned a2, unsigned a3,
                                         unsigned b0, unsigned b1) {
    asm volatile(
        "mma.sync.aligned.m16n8k16.row.col.f32.f16.f16.f32 "
        "{%0,%1,%2,%3}, {%4,%5,%6,%7}, {%8,%9}, {%0,%1,%2,%3};"
        : "+f"(c.x), "+f"(c.y), "+f"(c.z), "+f"(c.w)
        : "r"(a0), "r"(a1), "r"(a2), "r"(a3), "r"(b0), "r"(b1));
}

// ---------------- degree count + graph-size count (int4 vectorized) ----------------
__global__ void k_count(const int* __restrict__ ei, const int* __restrict__ batch) {
    int j = blockIdx.x * blockDim.x + threadIdx.x;
    if (j < Ee / 4) {
        int4 d = ((const int4*)(ei + Ee))[j];
        atomicAdd(&g_degcnt[d.x], 1);
        atomicAdd(&g_degcnt[d.y], 1);
        atomicAdd(&g_degcnt[d.z], 1);
        atomicAdd(&g_degcnt[d.w], 1);
    }
    if (j < Nn / 4) {
        int4 b = ((const int4*)batch)[j];
        atomicAdd(&g_cnt[b.x], 1.0f);
        atomicAdd(&g_cnt[b.y], 1.0f);
        atomicAdd(&g_cnt[b.z], 1.0f);
        atomicAdd(&g_cnt[b.w], 1.0f);
    }
}

// ---------------- fused: decoupled-lookback scan (blocks 0..195) + W1-projection
__global__ void __launch_bounds__(256) k_scan_proj(
    const float* __restrict__ emb0, const float* __restrict__ emb1,
    const float* __restrict__ emb2, const float* __restrict__ emb5,
    const float* __restrict__ W1) {
    int bid = blockIdx.x;
    int tid = threadIdx.x;

    if (bid >= SCAN_BLKS) {
        int idx = (bid - SCAN_BLKS) * 2 + (tid >> 7);
        if (idx >= 470) return;
        int c = tid & 127;
        const float* emb; int koff, v;
        if (idx < 96)       { emb = emb0; koff = 1;  v = idx; }
        else if (idx < 192) { emb = emb1; koff = 33; v = idx - 96; }
        else if (idx < 288) { emb = emb2; koff = 65; v = idx - 192; }
        else                { emb = emb5; koff = 97; v = idx - 288; }
        float acc = 0.0f;
#pragma unroll
        for (int j = 0; j < 32; j++)
            acc += emb[v * 32 + j] * W1[(koff + j) * Hh + c];
        g_P[(size_t)idx * Hh + c] = acc;
        return;
    }

    __shared__ int wsum[8];
    __shared__ int wred[8];
    int lane = tid & 31, wp = tid >> 5;
    int i = bid * 256 + tid;
    int v = (i < Nn) ? g_degcnt[i] : 0;
    int incl = warp_incl_scan(v, lane);
    if (lane == 31) wsum[wp] = incl;
    __syncthreads();
    int woff = 0, total = 0;
#pragma unroll
    for (int w = 0; w < 8; w++) {
        woff += (w < wp) ? wsum[w] : 0;
        total += wsum[w];
    }
    int excl = woff + incl - v;

    if (tid == 0) atomicExch(&g_sflag[bid], (total << 1) | 1);

    int mysum = 0;
    if (tid < bid) {
        int f;
        do { f = atomicAdd(&g_sflag[tid], 0); } while (!(f & 1));
        mysum = f >> 1;
    }
#pragma unroll
    for (int off = 16; off > 0; off >>= 1)
        mysum += __shfl_down_sync(0xFFFFFFFFu, mysum, off);
    if (lane == 0) wred[wp] = mysum;
    __syncthreads();
    int prefix = 0;
#pragma unroll
    for (int w = 0; w < 8; w++) prefix += wred[w];

    if (i < Nn) {
        g_base[i] = excl + prefix;
        g_dinv[i] = rsqrtf((float)g_degcnt[i] + 1.0f);
    }
    if (i == 0) g_base[Nn] = Ee;
}

// ---------------- fused: CSR edge placement + layer-1 hw production ----------------
__global__ void __launch_bounds__(256) k_place_layer1(
    const int* __restrict__ ei, const float* __restrict__ x,
    const float* __restrict__ W1) {
    int tid = threadIdx.x;
    if (blockIdx.x < E4BLK) {
        int j = blockIdx.x * 256 + tid;
        if (j >= Ee / 4) return;
        int4 s = ((const int4*)ei)[j];
        int4 d = ((const int4*)(ei + Ee))[j];
        g_esrc[g_base[d.x] + atomicAdd(&g_cursor[d.x], 1)] = s.x;
        g_esrc[g_base[d.y] + atomicAdd(&g_cursor[d.y], 1)] = s.y;
        g_esrc[g_base[d.z] + atomicAdd(&g_cursor[d.z], 1)] = s.z;
        g_esrc[g_base[d.w] + atomicAdd(&g_cursor[d.w], 1)] = s.w;
        return;
    }
    int node = (blockIdx.x - E4BLK) * 4 + (tid >> 6);
    if (node >= Nn) return;
    int c2 = tid & 63;
    int c0 = c2 * 2;
    const float* xr = x + (size_t)node * 5;
    float pos = xr[0];
    int i0 = (int)xr[1], i1 = (int)xr[2], i2 = (int)xr[3], i5 = (int)xr[4];
    const float* p0 = g_P + (size_t)i0 * Hh;
    const float* p1 = g_P + (size_t)(96 + i1) * Hh;
    const float* p2 = g_P + (size_t)(192 + i2) * Hh;
    const float* p5 = g_P + (size_t)(288 + i5) * Hh;
    float di = g_dinv[node];
    float va = (pos * W1[c0]     + p0[c0]     + p1[c0]     + p2[c0]     + p5[c0]) * di;
    float vb = (pos * W1[c0 + 1] + p0[c0 + 1] + p1[c0 + 1] + p2[c0 + 1] + p5[c0 + 1]) * di;
    g_hwh[(size_t)node * 64 + c2] = __floats2half2_rn(va, vb);
}

// ---------------- fused aggregation + self-loop + bias + BN partial stats ------
// uint4 row loads: 16 lanes per row, 2 rows per warp-load (half = lane>>4).
// Rows summed pairwise in fp16 (HADD2), converted once -> fp32 accumulators.
// Zero-row (Nn) padding keeps the loop branch-free; no remainder loop.
__global__ void __launch_bounds__(256) k_gather(int layer, const float* __restrict__ bias) {
    __shared__ float s_sum[8][132];
    __shared__ float s_sq[8][132];
    int tid = threadIdx.x;
    int wp = tid >> 5;
    int lane = tid & 31;
    int half = lane >> 4;          // 0/1: which row of each load pair
    int sl = lane & 15;            // 16B chunk within row; channels sl*8..sl*8+7
    int gw = blockIdx.x * 8 + wp;

    float4 o_lo = make_float4(0.f, 0.f, 0.f, 0.f);   // channels c0..c0+3 (c0=sl*8+half*4)
    int c0 = sl * 8 + half * 4;
    if (gw < Nn) {
        int s = g_base[gw], e = g_base[gw + 1];
        int deg = e - s;
        float di = g_dinv[gw];
        float acc8[8];
#pragma unroll
        for (int k = 0; k < 8; k++) acc8[k] = 0.f;
        const uint4* hw4 = (const uint4*)g_hwh;     // row r starts at hw4[r*16]

        for (int base = 0; base < deg; base += 32) {
            int rem = deg - base; if (rem > 32) rem = 32;
            int idx = (lane < rem) ? g_esrc[s + base + lane] : Nn;
            int slots = (rem + 15) & ~15;           // 16 or 32
            for (int j = 0; j < slots; j += 16) {
                uint4 r[8];
#pragma unroll
                for (int q = 0; q < 8; q++) {
                    int row = __shfl_sync(0xFFFFFFFFu, idx, j + 2 * q + half);
                    r[q] = hw4[(size_t)row * 16 + sl];
                }
#pragma unroll
                for (int p = 0; p < 4; p++) {
                    uint4 ra = r[2 * p], rb = r[2 * p + 1];
                    __half2 s0 = __hadd2(*(__half2*)&ra.x, *(__half2*)&rb.x);
                    __half2 s1 = __hadd2(*(__half2*)&ra.y, *(__half2*)&rb.y);
                    __half2 s2 = __hadd2(*(__half2*)&ra.z, *(__half2*)&rb.z);
                    __half2 s3 = __hadd2(*(__half2*)&ra.w, *(__half2*)&rb.w);
                    float2 f0 = __half22float2(s0), f1 = __half22float2(s1);
                    float2 f2 = __half22float2(s2), f3 = __half22float2(s3);
                    acc8[0] += f0.x; acc8[1] += f0.y;
                    acc8[2] += f1.x; acc8[3] += f1.y;
                    acc8[4] += f2.x; acc8[5] += f2.y;
                    acc8[6] += f3.x; acc8[7] += f3.y;
                }
            }
        }
        // self row (scaled by dinv[gw] already); half 1 reads the zero row
        {
            int rowself = (half == 0) ? gw : Nn;
            uint4 rs = hw4[(size_t)rowself * 16 + sl];
            float2 f0 = __half22float2(*(__half2*)&rs.x);
            float2 f1 = __half22float2(*(__half2*)&rs.y);
            float2 f2 = __half22float2(*(__half2*)&rs.z);
            float2 f3 = __half22float2(*(__half2*)&rs.w);
            acc8[0] += f0.x; acc8[1] += f0.y;
            acc8[2] += f1.x; acc8[3] += f1.y;
            acc8[4] += f2.x; acc8[5] += f2.y;
            acc8[6] += f3.x; acc8[7] += f3.y;
        }
        // combine the two half-warps (each summed half the rows)
#pragma unroll
        for (int k = 0; k < 8; k++)
            acc8[k] += __shfl_xor_sync(0xFFFFFFFFu, acc8[k], 16);

        float4 bv = *(const float4*)(bias + c0);
        o_lo.x = acc8[half * 4 + 0] * di + bv.x;
        o_lo.y = acc8[half * 4 + 1] * di + bv.y;
        o_lo.z = acc8[half * 4 + 2] * di + bv.z;
        o_lo.w = acc8[half * 4 + 3] * di + bv.w;
        *(float4*)(g_agg + (size_t)gw * Hh + c0) = o_lo;
    }
    // BN partial sums (each lane owns 4 distinct channels c0..c0+3)
    *(float4*)(&s_sum[wp][c0]) = o_lo;
    float4 sq = make_float4(o_lo.x * o_lo.x, o_lo.y * o_lo.y,
                            o_lo.z * o_lo.z, o_lo.w * o_lo.w);
    *(float4*)(&s_sq[wp][c0]) = sq;
    __syncthreads();
    if (tid < 128) {
        float s = 0.f, q = 0.f;
#pragma unroll
        for (int w = 0; w < 8; w++) { s += s_sum[w][tid]; q += s_sq[w][tid]; }
        atomicAdd(&g_bnsum[layer * Hh + tid], s);
        atomicAdd(&g_bnsq[layer * Hh + tid], q);
    }
}

// ---------------- tensor-core GEMM: relu(bn(A)) @ W -> hw (pre-scaled fp16) ----------------
#define GEMM_SMEM (2 * 128 * Pp * 2)
__global__ void __launch_bounds__(256)
k_gemm(int layer, const float* __restrict__ gamma, const float* __restrict__ beta,
       const float* __restrict__ W) {
    extern __shared__ __half smh[];
    __half* As = smh;                 // 128 x Pp
    __half* Wt = smh + 128 * Pp;      // 128 x Pp (transposed W: Wt[n][k])
    __shared__ float s_scale[128];
    __shared__ float s_shift[128];
    int tid = threadIdx.x;
    int row0 = blockIdx.x * 128;

    if (tid < 128) {
        float mean = g_bnsum[layer * Hh + tid] * (1.0f / Nn);
        float var = g_bnsq[layer * Hh + tid] * (1.0f / Nn) - mean * mean;
        float sc = gamma[tid] * rsqrtf(var + EPSf);
        s_scale[tid] = sc;
        s_shift[tid] = beta[tid] - mean * sc;
    }

    for (int t = tid; t < 128 * 32; t += 256) {
        int k = t >> 5, n0 = (t & 31) * 4;
        float4 wv = ((const float4*)W)[t];
        Wt[(n0 + 0) * Pp + k] = __float2half_rn(wv.x);
        Wt[(n0 + 1) * Pp + k] = __float2half_rn(wv.y);
        Wt[(n0 + 2) * Pp + k] = __float2half_rn(wv.z);
        Wt[(n0 + 3) * Pp + k] = __float2half_rn(wv.w);
    }
    __syncthreads();

    for (int t = tid; t < 128 * 32; t += 256) {
        int r = t >> 5, q = t & 31;
        int grow = row0 + r;
        float4 v = make_float4(0.f, 0.f, 0.f, 0.f);
        if (grow < Nn) {
            v = ((const float4*)(g_agg + (size_t)grow * Hh))[q];
            float4 sc = ((const float4*)s_scale)[q];
            float4 sh = ((const float4*)s_shift)[q];
            v.x = fmaxf(v.x * sc.x + sh.x, 0.f);
            v.y = fmaxf(v.y * sc.y + sh.y, 0.f);
            v.z = fmaxf(v.z * sc.z + sh.z, 0.f);
            v.w = fmaxf(v.w * sc.w + sh.w, 0.f);
        }
        __half2 h0 = __floats2half2_rn(v.x, v.y);
        __half2 h1 = __floats2half2_rn(v.z, v.w);
        uint2 u = make_uint2(*(unsigned*)&h0, *(unsigned*)&h1);
        *(uint2*)(As + r * Pp + q * 4) = u;
    }
    __syncthreads();

    int wp = tid >> 5;
    int lane = tid & 31;
    int g = lane >> 2;
    int tg = lane & 3;

    float4 c[16];
#pragma unroll
    for (int nt = 0; nt < 16; nt++) c[nt] = make_float4(0.f, 0.f, 0.f, 0.f);

    const __half* Abase = As + (wp * 16 + g) * Pp + 2 * tg;
#pragma unroll
    for (int kk = 0; kk < 8; kk++) {
        const __half* Ar = Abase + kk * 16;
        unsigned a0 = *(const unsigned*)(Ar);
        unsigned a1 = *(const unsigned*)(Ar + 8 * Pp);
        unsigned a2 = *(const unsigned*)(Ar + 8);
        unsigned a3 = *(const unsigned*)(Ar + 8 * Pp + 8);
        const __half* Bb = Wt + g * Pp + kk * 16 + 2 * tg;
#pragma unroll
        for (int nt = 0; nt < 16; nt++) {
            const __half* Br = Bb + nt * 8 * Pp;
            unsigned b0 = *(const unsigned*)(Br);
            unsigned b1 = *(const unsigned*)(Br + 8);
            mma16816(c[nt], a0, a1, a2, a3, b0, b1);
        }
    }

    int r_lo = row0 + wp * 16 + g;
    int r_hi = r_lo + 8;
    bool ok_lo = (r_lo < Nn), ok_hi = (r_hi < Nn);
    float d_lo = ok_lo ? g_dinv[r_lo] : 0.f;
    float d_hi = ok_hi ? g_dinv[r_hi] : 0.f;
    __half2* out_lo = g_hwh + (size_t)r_lo * 64 + tg;
    __half2* out_hi = g_hwh + (size_t)r_hi * 64 + tg;
#pragma unroll
    for (int nt = 0; nt < 16; nt++) {
        if (ok_lo) out_lo[nt * 4] = __floats2half2_rn(c[nt].x * d_lo, c[nt].y * d_lo);
        if (ok_hi) out_hi[nt * 4] = __floats2half2_rn(c[nt].z * d_hi, c[nt].w * d_hi);
    }
}

// ---------------- pooling: batch is sorted -> run-length accumulate ----------------
__global__ void k_pool(const int* __restrict__ batch,
                       const float* __restrict__ gamma, const float* __restrict__ beta) {
    __shared__ int sb[128];
    int c = threadIdx.x;
    int r0 = blockIdx.x * 128;
    int nrows = min(128, Nn - r0);
    if (c < nrows) sb[c] = batch[r0 + c];
    float mean = g_bnsum[2 * Hh + c] * (1.0f / Nn);
    float var = g_bnsq[2 * Hh + c] * (1.0f / Nn) - mean * mean;
    float sc = gamma[c] * rsqrtf(var + EPSf);
    float sh = beta[c] - mean * sc;
    __syncthreads();
    float acc = 0.f;
    int cur = sb[0];
    for (int r = 0; r < nrows; r++) {
        int gr = sb[r];
        if (gr != cur) { atomicAdd(&g_pooled[cur * Hh + c], acc); acc = 0.f; cur = gr; }
        float v = g_agg[(size_t)(r0 + r) * Hh + c];
        acc += fmaxf(v * sc + sh, 0.f);
    }
    atomicAdd(&g_pooled[cur * Hh + c], acc);
}

// ---------------- final FC + TAIL ZEROING for next replay ----------------
__global__ void k_fc(const float* __restrict__ fcW, const float* __restrict__ fcb,
                     float* __restrict__ out) {
    int g = blockIdx.x, c = threadIdx.x;
    int t = g * 128 + c;
    float v = g_pooled[g * Hh + c] / fmaxf(g_cnt[g], 1.0f);
    g_pooled[g * Hh + c] = 0.0f;
    __shared__ float s0[128], s1[128], s2[128];
    s0[c] = v * fcW[c * 3 + 0];
    s1[c] = v * fcW[c * 3 + 1];
    s2[c] = v * fcW[c * 3 + 2];
    __syncthreads();
    for (int off = 64; off > 0; off >>= 1) {
        if (c < off) { s0[c] += s0[c + off]; s1[c] += s1[c + off]; s2[c] += s2[c + off]; }
        __syncthreads();
    }
    if (c == 0) {
        out[g * 3 + 0] = s0[0] + fcb[0];
        out[g * 3 + 1] = s1[0] + fcb[1];
        out[g * 3 + 2] = s2[0] + fcb[2];
        g_cnt[g] = 0.0f;
    }
    if (t < Nn) { g_degcnt[t] = 0; g_cursor[t] = 0; }
    if (t < SCAN_BLKS) g_sflag[t] = 0;
    if (t < 3 * Hh) { g_bnsum[t] = 0.0f; g_bnsq[t] = 0.0f; }
}

// ---------------- launch ----------------
extern "C" void kernel_launch(void* const* d_in, const int* in_sizes, int n_in,
                              void* d_out, int out_size) {
    const float* x     = (const float*)d_in[0];
    const int*   ei    = (const int*)  d_in[1];
    const int*   batch = (const int*)  d_in[2];
    const float* emb0  = (const float*)d_in[3];
    const float* emb1  = (const float*)d_in[4];
    const float* emb2  = (const float*)d_in[5];
    const float* emb5  = (const float*)d_in[6];
    const float* W1    = (const float*)d_in[7];
    const float* b1    = (const float*)d_in[8];
    const float* W2    = (const float*)d_in[9];
    const float* b2    = (const float*)d_in[10];
    const float* W3    = (const float*)d_in[11];
    const float* b3    = (const float*)d_in[12];
    const float* g1    = (const float*)d_in[13];
    const float* be1   = (const float*)d_in[14];
    const float* g2    = (const float*)d_in[15];
    const float* be2   = (const float*)d_in[16];
    const float* g3    = (const float*)d_in[17];
    const float* be3   = (const float*)d_in[18];
    const float* fcW   = (const float*)d_in[19];
    const float* fcb   = (const float*)d_in[20];
    float* out = (float*)d_out;

    cudaFuncSetAttribute(k_gemm, cudaFuncAttributeMaxDynamicSharedMemorySize, GEMM_SMEM);

    const int nblk = (Nn + 127) / 128;          // 391
    const int gblk = (Nn + 7) / 8;              // gather blocks (8 warps = 8 nodes)

    // 10-kernel critical path
    k_count<<<E4BLK, 256>>>(ei, batch);
    k_scan_proj<<<SCAN_BLKS + PROJ_BLKS, 256>>>(emb0, emb1, emb2, emb5, W1);
    k_place_layer1<<<E4BLK + L1BLK, 256>>>(ei, x, W1);

    k_gather<<<gblk, 256>>>(0, b1);
    k_gemm<<<nblk, 256, GEMM_SMEM>>>(0, g1, be1, W2);
    k_gather<<<gblk, 256>>>(1, b2);
    k_gemm<<<nblk, 256, GEMM_SMEM>>>(1, g2, be2, W3);
    k_gather<<<gblk, 256>>>(2, b3);

    k_pool<<<nblk, 128>>>(batch, g3, be3);
    k_fc<<<Gg, 128>>>(fcW, fcb, out);
}